// round 5
// baseline (speedup 1.0000x reference)
#include <cuda_runtime.h>
#include <cuda_bf16.h>
#include <math.h>
#include <cstdint>

// Problem constants
#define NQ   100
#define NT   197
#define BSZ  128
#define E    768
#define NH   12
#define HD   64
#define BH   (BSZ*NH)          // 1536

// ---------------------------------------------------------------------------
// Device scratch (no cudaMalloc allowed). q/k/v stay row-major [M][E].
// ---------------------------------------------------------------------------
__device__ float g_qt[NQ * BSZ * E];
__device__ float g_kt[NT * BSZ * E];
__device__ float g_vt[NT * BSZ * E];
__device__ float g_qmT[NQ * NT];
__device__ float g_xmT[NT * NQ];
__device__ float g_y[NQ * BSZ * E];

// ---------------------------------------------------------------------------
// mma.sync fp16 GEMM:  C[M,N=768] = A[M,K=768] @ W[N,K]^T + bias[N]
// CTA tile 128x128, 8 warps (2M x 4N), warp tile 64x32, m16n8k16 f16 MMA
// with fp32 accumulate (fp16 u = 2^-11 == tf32 precision for N(0,1) data).
// 3-stage cp.async pipeline, K-chunks of 32 floats, fp32 in SMEM,
// cvt.rn.f16x2 on fragment load (adjacent pairs -> LDS.64 + 1 cvt).
// ---------------------------------------------------------------------------
#define PAD       36                       // padded row stride (floats)
#define MAT_F     (128 * PAD)              // floats per matrix tile (A or B)
#define STG_F     (2 * MAT_F)              // floats per stage
#define GEMM_SMEM (3 * STG_F * 4)          // 110592 bytes

__device__ __forceinline__ void cpa16(uint32_t dst, const void* src) {
    asm volatile("cp.async.cg.shared.global [%0], [%1], 16;" :: "r"(dst), "l"(src));
}
__device__ __forceinline__ uint32_t smem_u32(const void* p) {
    uint32_t a;
    asm("{ .reg .u64 t; cvta.to.shared.u64 t, %1; cvt.u32.u64 %0, t; }"
        : "=r"(a) : "l"(p));
    return a;
}
// pack two fp32 into one half2 register: lo = first k element, hi = second
__device__ __forceinline__ uint32_t pack_h2(float lo, float hi) {
    uint32_t r;
    asm("cvt.rn.f16x2.f32 %0, %1, %2;" : "=r"(r) : "f"(hi), "f"(lo));
    return r;
}
__device__ __forceinline__ void mma_f16(float* c, const uint32_t* a, const uint32_t* b) {
    asm volatile(
        "mma.sync.aligned.m16n8k16.row.col.f32.f16.f16.f32 "
        "{%0,%1,%2,%3}, {%4,%5,%6,%7}, {%8,%9}, {%0,%1,%2,%3};"
        : "+f"(c[0]), "+f"(c[1]), "+f"(c[2]), "+f"(c[3])
        : "r"(a[0]), "r"(a[1]), "r"(a[2]), "r"(a[3]), "r"(b[0]), "r"(b[1]));
}

__global__ __launch_bounds__(256, 2)
void gemm_mma(const float* __restrict__ A, const float* __restrict__ W,
              const float* __restrict__ bias, float* __restrict__ C)
{
    extern __shared__ float sm[];
    const int tid  = threadIdx.x;
    const int lane = tid & 31;
    const int wid  = tid >> 5;
    const int m0 = blockIdx.y * 128, n0 = blockIdx.x * 128;
    const int wm = (wid >> 2) * 64;          // warp M offset (0 / 64)
    const int wn = (wid & 3) * 32;           // warp N offset (0..96)

    // producer mapping: each thread loads 64B of one row of A and of B per stage
    const int prow = tid >> 1;               // 0..127
    const int phal = (tid & 1) * 16;         // float offset within row (0 / 16)
    const float* gA = A + (size_t)(m0 + prow) * E + phal;
    const float* gB = W + (size_t)(n0 + prow) * E + phal;
    const uint32_t sbase = smem_u32(sm);
    const uint32_t sArow = sbase + (prow * PAD + phal) * 4;
    const uint32_t sBrow = sArow + MAT_F * 4;

#define LOAD_STAGE(st, kc) do { \
    const uint32_t so = (uint32_t)(st) * (STG_F * 4); \
    const float* ga = gA + (kc) * 32; \
    const float* gb = gB + (kc) * 32; \
    cpa16(sArow + so,      ga);      cpa16(sArow + so + 16, ga + 4); \
    cpa16(sArow + so + 32, ga + 8);  cpa16(sArow + so + 48, ga + 12); \
    cpa16(sBrow + so,      gb);      cpa16(sBrow + so + 16, gb + 4); \
    cpa16(sBrow + so + 32, gb + 8);  cpa16(sBrow + so + 48, gb + 12); \
    asm volatile("cp.async.commit_group;"); \
} while (0)

    LOAD_STAGE(0, 0);
    LOAD_STAGE(1, 1);
    LOAD_STAGE(2, 2);

    float acc[4][4][4];
#pragma unroll
    for (int i = 0; i < 4; i++)
#pragma unroll
        for (int j = 0; j < 4; j++)
#pragma unroll
            for (int k = 0; k < 4; k++) acc[i][j][k] = 0.0f;

    const int r = lane >> 2;     // 0..7
    const int q = lane & 3;      // 0..3

    for (int kc = 0; kc < 24; kc++) {
        asm volatile("cp.async.wait_group 2;");
        __syncthreads();
        const float* sA = sm + (kc % 3) * STG_F;
        const float* sB = sA + MAT_F;

#pragma unroll
        for (int s = 0; s < 2; s++) {            // two K=16 steps per 32-float chunk
            const int k0 = s * 16 + 2 * q;
            uint32_t bf[4][2];
#pragma unroll
            for (int nt = 0; nt < 4; nt++) {
                const float* bp = sB + (wn + nt * 8 + r) * PAD + k0;
                float2 u0 = *(const float2*)bp;
                float2 u1 = *(const float2*)(bp + 8);
                bf[nt][0] = pack_h2(u0.x, u0.y);
                bf[nt][1] = pack_h2(u1.x, u1.y);
            }
#pragma unroll
            for (int mt = 0; mt < 4; mt++) {
                const float* ap = sA + (wm + mt * 16 + r) * PAD + k0;
                float2 v0 = *(const float2*)ap;
                float2 v1 = *(const float2*)(ap + 8 * PAD);
                float2 v2 = *(const float2*)(ap + 8);
                float2 v3 = *(const float2*)(ap + 8 * PAD + 8);
                uint32_t af[4];
                af[0] = pack_h2(v0.x, v0.y);
                af[1] = pack_h2(v1.x, v1.y);
                af[2] = pack_h2(v2.x, v2.y);
                af[3] = pack_h2(v3.x, v3.y);
#pragma unroll
                for (int nt = 0; nt < 4; nt++)
                    mma_f16(acc[mt][nt], af, bf[nt]);
            }
        }
        __syncthreads();
        if (kc + 3 < 24) {
            LOAD_STAGE(kc % 3, kc + 3);
        } else {
            asm volatile("cp.async.commit_group;");
        }
    }

    // epilogue: bias add + row-major store (float2 per c-pair)
#pragma unroll
    for (int mt = 0; mt < 4; mt++) {
        const int row = m0 + wm + mt * 16 + r;
#pragma unroll
        for (int nt = 0; nt < 4; nt++) {
            const int col = n0 + wn + nt * 8 + 2 * q;
            const float b0 = bias[col], b1 = bias[col + 1];
            *(float2*)&C[(size_t)row * E + col] =
                make_float2(acc[mt][nt][0] + b0, acc[mt][nt][1] + b1);
            *(float2*)&C[(size_t)(row + 8) * E + col] =
                make_float2(acc[mt][nt][2] + b0, acc[mt][nt][3] + b1);
        }
    }
#undef LOAD_STAGE
}

// ---------------------------------------------------------------------------
// Normalize + transpose mapper matrices.
// ---------------------------------------------------------------------------
__global__ void norm_map(const float* __restrict__ qm, const float* __restrict__ xm,
                         float* __restrict__ qmT, float* __restrict__ xmT)
{
    int row  = blockIdx.x * (blockDim.x >> 5) + (threadIdx.x >> 5);
    int lane = threadIdx.x & 31;
    if (row < NT) {
        const float* x = qm + row * NQ;
        float ss = 0.0f;
        for (int i = lane; i < NQ; i += 32) { float v = x[i]; ss += v * v; }
#pragma unroll
        for (int o = 16; o; o >>= 1) ss += __shfl_xor_sync(0xffffffffu, ss, o);
        float s = 1.0f / fmaxf(sqrtf(ss), 1e-12f);
        for (int i = lane; i < NQ; i += 32) qmT[i * NT + row] = x[i] * s;
    } else if (row < NT + NQ) {
        int r = row - NT;
        const float* x = xm + r * NT;
        float ss = 0.0f;
        for (int i = lane; i < NT; i += 32) { float v = x[i]; ss += v * v; }
#pragma unroll
        for (int o = 16; o; o >>= 1) ss += __shfl_xor_sync(0xffffffffu, ss, o);
        float s = 1.0f / fmaxf(sqrtf(ss), 1e-12f);
        for (int i = lane; i < NT; i += 32) xmT[i * NQ + r] = x[i] * s;
    }
}

// ---------------------------------------------------------------------------
// Fused per-(b,h) attention with in-SMEM q/k L2 normalization.
// q/k/v are row-major [tok*BSZ+b][E]; gather 64-float rows per token.
// ---------------------------------------------------------------------------
#define SQP 101
#define SKP 197
#define SAP 65
#define ATTN_SMEM_FLOATS (64*SQP + 64*SKP + 64*SKP + 64*SAP)   // 35840
#define ROWSTR ((size_t)BSZ * E)                               // 98304

__global__ __launch_bounds__(512, 1)
void attn_kernel(const float* __restrict__ q_t, const float* __restrict__ k_t,
                 const float* __restrict__ v_t, const float* __restrict__ qmT,
                 const float* __restrict__ xmT, const float* __restrict__ temp,
                 float* __restrict__ y)
{
    extern __shared__ float sm[];
    float* sQ = sm;
    float* sK = sQ + 64 * SQP;
    float* sM = sK + 64 * SKP;
    float* sA = sM + 64 * SKP;

    const int bh = blockIdx.x;
    const int b  = bh / NH;
    const int h  = bh % NH;
    const float* qp = q_t + (size_t)b * E + h * HD;
    const float* kp = k_t + (size_t)b * E + h * HD;
    const float* vp = v_t + (size_t)b * E + h * HD;

    const int tid  = threadIdx.x;
    const int w    = tid >> 5;
    const int lane = tid & 31;

    // Phase 0: gather q and k tiles (64 contiguous floats per token)
    for (int i = tid; i < NQ * 64; i += 512) {
        int tok = i >> 6, d = i & 63;
        sQ[d * SQP + tok] = qp[(size_t)tok * ROWSTR + d];
    }
    for (int i = tid; i < NT * 64; i += 512) {
        int tok = i >> 6, d = i & 63;
        sK[d * SKP + tok] = kp[(size_t)tok * ROWSTR + d];
    }
    __syncthreads();

    // Phase 0.5: fused L2 normalization over tokens
    for (int rr = w; rr < 128; rr += 16) {
        float* x; int L;
        if (rr < 64) { x = sQ + rr * SQP; L = NQ; }
        else         { x = sK + (rr - 64) * SKP; L = NT; }
        float ss = 0.0f;
        for (int i = lane; i < L; i += 32) { float v = x[i]; ss += v * v; }
#pragma unroll
        for (int o = 16; o; o >>= 1) ss += __shfl_xor_sync(0xffffffffu, ss, o);
        float sc = 1.0f / fmaxf(sqrtf(ss), 1e-12f);
        for (int i = lane; i < L; i += 32) x[i] *= sc;
    }
    __syncthreads();

    // Phase 1: qm[d,t] = sum_q sQ[d,q] * qmT[q,t]
    {
        const int d0 = (w >> 1) * 8;
        const int tb = lane + ((w & 1) << 5);
        for (int t = tb; t < NT; t += 64) {
            float acc[8] = {0,0,0,0,0,0,0,0};
            for (int qq = 0; qq < NQ; qq++) {
                float m = qmT[qq * NT + t];
#pragma unroll
                for (int i = 0; i < 8; i++)
                    acc[i] = fmaf(sQ[(d0 + i) * SQP + qq], m, acc[i]);
            }
#pragma unroll
            for (int i = 0; i < 8; i++) sM[(d0 + i) * SKP + t] = acc[i];
        }
    }
    __syncthreads();

    // Phase 2: attn[d,e] = temp[h] * sum_t qm[d,t] * kn[e,t]
    {
        const float tval = temp[h];
        const int e0 = (tid & 15) << 2;
        const int d0 = (tid >> 4) << 1;
        float acc[2][4] = {{0,0,0,0},{0,0,0,0}};
        for (int t = 0; t < NT; t++) {
            float a0 = sM[d0 * SKP + t];
            float a1 = sM[(d0 + 1) * SKP + t];
            float bv[4];
#pragma unroll
            for (int j = 0; j < 4; j++) bv[j] = sK[(e0 + j) * SKP + t];
#pragma unroll
            for (int j = 0; j < 4; j++) {
                acc[0][j] = fmaf(a0, bv[j], acc[0][j]);
                acc[1][j] = fmaf(a1, bv[j], acc[1][j]);
            }
        }
#pragma unroll
        for (int i = 0; i < 2; i++)
#pragma unroll
            for (int j = 0; j < 4; j++)
                sA[(d0 + i) * SAP + e0 + j] = acc[i][j] * tval;
    }
    __syncthreads();

    // Phase 3: softmax rows of sA (threads 0..63) while others gather v into sK
    if (tid < 64) {
        float* rr = sA + tid * SAP;
        float mx = rr[0];
#pragma unroll 8
        for (int e = 1; e < 64; e++) mx = fmaxf(mx, rr[e]);
        float s = 0.0f;
        for (int e = 0; e < 64; e++) { float ev = expf(rr[e] - mx); rr[e] = ev; s += ev; }
        float inv = 1.0f / s;
        for (int e = 0; e < 64; e++) rr[e] *= inv;
    } else {
        for (int i = tid - 64; i < NT * 64; i += 448) {
            int tok = i >> 6, d = i & 63;
            sK[d * SKP + tok] = vp[(size_t)tok * ROWSTR + d];
        }
    }
    __syncthreads();

    // Phase 4: x[d,t] = sum_e attn[d,e] * v[e,t]  -> overwrite sM
    {
        const int d0 = (w >> 1) * 8;
        const int tb = lane + ((w & 1) << 5);
        for (int t = tb; t < NT; t += 64) {
            float acc[8] = {0,0,0,0,0,0,0,0};
            for (int e = 0; e < 64; e++) {
                float vv = sK[e * SKP + t];
#pragma unroll
                for (int i = 0; i < 8; i++)
                    acc[i] = fmaf(sA[(d0 + i) * SAP + e], vv, acc[i]);
            }
#pragma unroll
            for (int i = 0; i < 8; i++) sM[(d0 + i) * SKP + t] = acc[i];
        }
    }
    __syncthreads();

    // Phase 5: out[d,q] = sum_t x[d,t] * xmT[t,q]; write y[(q*BSZ+b)*E + h*64 + d]
    {
        const int q0 = w * 8;
        if (q0 < NQ) {
            const int qlim = NQ - q0;
            const int d = lane;
            float acc0[8] = {0,0,0,0,0,0,0,0};
            float acc1[8] = {0,0,0,0,0,0,0,0};
            for (int t = 0; t < NT; t++) {
                float x0 = sM[d * SKP + t];
                float x1 = sM[(d + 32) * SKP + t];
#pragma unroll
                for (int j = 0; j < 8; j++) {
                    float xv = (j < qlim) ? xmT[t * NQ + q0 + j] : 0.0f;
                    acc0[j] = fmaf(x0, xv, acc0[j]);
                    acc1[j] = fmaf(x1, xv, acc1[j]);
                }
            }
#pragma unroll
            for (int j = 0; j < 8; j++) {
                if (j < qlim) {
                    size_t base = ((size_t)(q0 + j) * BSZ + b) * E + h * HD;
                    y[base + d]      = acc0[j];
                    y[base + d + 32] = acc1[j];
                }
            }
        }
    }
}

// ---------------------------------------------------------------------------
// Launch
// ---------------------------------------------------------------------------
extern "C" void kernel_launch(void* const* d_in, const int* in_sizes, int n_in,
                              void* d_out, int out_size)
{
    const float* query = (const float*)d_in[0];
    const float* key   = (const float*)d_in[1];
    const float* value = (const float*)d_in[2];
    const float* ipw   = (const float*)d_in[3];
    const float* ipb   = (const float*)d_in[4];
    const float* opw   = (const float*)d_in[5];
    const float* opb   = (const float*)d_in[6];
    const float* temp  = (const float*)d_in[7];
    const float* qmap  = (const float*)d_in[8];
    const float* xmap  = (const float*)d_in[9];
    float* out = (float*)d_out;

    float *qt, *kt, *vt, *qmT, *xmT, *y;
    cudaGetSymbolAddress((void**)&qt,  g_qt);
    cudaGetSymbolAddress((void**)&kt,  g_kt);
    cudaGetSymbolAddress((void**)&vt,  g_vt);
    cudaGetSymbolAddress((void**)&qmT, g_qmT);
    cudaGetSymbolAddress((void**)&xmT, g_xmT);
    cudaGetSymbolAddress((void**)&y,   g_y);

    cudaFuncSetAttribute(gemm_mma, cudaFuncAttributeMaxDynamicSharedMemorySize, GEMM_SMEM);
    cudaFuncSetAttribute(attn_kernel, cudaFuncAttributeMaxDynamicSharedMemorySize,
                         ATTN_SMEM_FLOATS * sizeof(float));

    // 1) Projections (mma.sync fp16, fp32 accumulate), row-major outputs
    dim3 gq(6, (NQ * BSZ) / 128);   // (6, 100)
    dim3 gk(6, (NT * BSZ) / 128);   // (6, 197)
    gemm_mma<<<gq, 256, GEMM_SMEM>>>(query, ipw,             ipb,         qt);
    gemm_mma<<<gk, 256, GEMM_SMEM>>>(key,   ipw + E * E,     ipb + E,     kt);
    gemm_mma<<<gk, 256, GEMM_SMEM>>>(value, ipw + 2 * E * E, ipb + 2 * E, vt);

    // 2) Normalize + transpose mapper matrices
    norm_map<<<(NT + NQ + 7) / 8, 256>>>(qmap, xmap, qmT, xmT);

    // 3) Fused attention per (b,h) (includes q/k L2 norm)
    attn_kernel<<<BH, 512, ATTN_SMEM_FLOATS * sizeof(float)>>>(qt, kt, vt, qmT, xmT, temp, y);

    // 4) Output projection -> d_out
    gemm_mma<<<gq, 256, GEMM_SMEM>>>(y, opw, opb, out);
}

// round 7
// speedup vs baseline: 1.3533x; 1.3533x over previous
#include <cuda_runtime.h>
#include <cuda_fp16.h>
#include <math.h>
#include <cstdint>

// Problem constants
#define NQ   100
#define NT   197
#define BSZ  128
#define E    768
#define NH   12
#define HD   64
#define BH   (BSZ*NH)          // 1536

// ---------------------------------------------------------------------------
// Device scratch (no cudaMalloc allowed)
// ---------------------------------------------------------------------------
__device__ float  g_qt[NQ * BSZ * E];      // fp32 GEMM outputs (attn inputs)
__device__ float  g_kt[NT * BSZ * E];
__device__ float  g_vt[NT * BSZ * E];
__device__ float  g_qmT[NQ * NT];
__device__ float  g_xmT[NT * NQ];
__device__ __half g_qh[NQ * BSZ * E];      // fp16 GEMM inputs
__device__ __half g_kh[NT * BSZ * E];
__device__ __half g_vh[NT * BSZ * E];
__device__ __half g_wh[3 * E * E];         // fp16 in_proj_weight
__device__ __half g_owh[E * E];            // fp16 out_proj_weight
__device__ __half g_yh[NQ * BSZ * E];      // fp16 attention output

// ---------------------------------------------------------------------------
// fp32 -> fp16 conversion (pure bandwidth)
// ---------------------------------------------------------------------------
__global__ void f2h(const float4* __restrict__ in, __half2* __restrict__ out, int n4)
{
    int i = blockIdx.x * blockDim.x + threadIdx.x;
    if (i < n4) {
        float4 v = in[i];
        out[2 * i]     = __floats2half2_rn(v.x, v.y);
        out[2 * i + 1] = __floats2half2_rn(v.z, v.w);
    }
}

// ---------------------------------------------------------------------------
// fp16 mma.sync GEMM:  C[M,N=768] = A[M,768] @ W[N,768]^T + bias[N]  (fp32 out)
// CTA 128x128, 8 warps (2M x 4N), warp tile 64x32, m16n8k16, ldmatrix frags.
// 4-stage cp.async ring (fp16 SMEM, 20KB/stage), one syncthreads per K-chunk.
// ---------------------------------------------------------------------------
#define PADH      40                        // halves per SMEM row (80B)
#define MAT_H     (128 * PADH)              // halves per matrix tile
#define STG_B     (2 * MAT_H * 2)           // bytes per stage  = 20480
#define GEMM_SMEM (4 * STG_B)               // 81920 bytes

__device__ __forceinline__ uint32_t smem_u32(const void* p) {
    uint32_t a;
    asm("{ .reg .u64 t; cvta.to.shared.u64 t, %1; cvt.u32.u64 %0, t; }"
        : "=r"(a) : "l"(p));
    return a;
}
__device__ __forceinline__ void cpa16(uint32_t dst, const void* src) {
    asm volatile("cp.async.cg.shared.global [%0], [%1], 16;" :: "r"(dst), "l"(src));
}
__device__ __forceinline__ void ldsm4(uint32_t& r0, uint32_t& r1, uint32_t& r2,
                                      uint32_t& r3, uint32_t addr) {
    asm volatile("ldmatrix.sync.aligned.m8n8.x4.shared.b16 {%0,%1,%2,%3}, [%4];"
                 : "=r"(r0), "=r"(r1), "=r"(r2), "=r"(r3) : "r"(addr));
}
__device__ __forceinline__ void mma_f16(float* c, const uint32_t* a, const uint32_t* b) {
    asm volatile(
        "mma.sync.aligned.m16n8k16.row.col.f32.f16.f16.f32 "
        "{%0,%1,%2,%3}, {%4,%5,%6,%7}, {%8,%9}, {%0,%1,%2,%3};"
        : "+f"(c[0]), "+f"(c[1]), "+f"(c[2]), "+f"(c[3])
        : "r"(a[0]), "r"(a[1]), "r"(a[2]), "r"(a[3]), "r"(b[0]), "r"(b[1]));
}

__global__ __launch_bounds__(256, 2)
void gemm_h(const __half* __restrict__ A, const __half* __restrict__ W,
            const float* __restrict__ bias, float* __restrict__ C)
{
    extern __shared__ __half smh[];
    const uint32_t sb = smem_u32(smh);
    const int tid  = threadIdx.x;
    const int lane = tid & 31;
    const int wid  = tid >> 5;
    const int m0 = blockIdx.y * 128, n0 = blockIdx.x * 128;
    const int wm = (wid >> 2) * 64;          // warp M offset
    const int wn = (wid & 3) * 32;           // warp N offset

    // producers: each thread cp.asyncs 2x16B of A and 2x16B of B per stage
    const int prow = tid >> 1;               // 0..127 (row of A tile and of B tile)
    const int pseg = (tid & 1) * 16;         // half-offset within 32-half row
    const __half* gA = A + (size_t)(m0 + prow) * E + pseg;
    const __half* gB = W + (size_t)(n0 + prow) * E + pseg;
    const uint32_t sAa = sb + (prow * PADH + pseg) * 2;
    const uint32_t sBa = sAa + MAT_H * 2;

#define LOAD_STAGE(st, kc) do { \
    const uint32_t so = (uint32_t)(st) * STG_B; \
    const __half* ga = gA + (kc) * 32; \
    const __half* gb = gB + (kc) * 32; \
    cpa16(sAa + so,      ga);     cpa16(sAa + so + 16, ga + 8); \
    cpa16(sBa + so,      gb);     cpa16(sBa + so + 16, gb + 8); \
    asm volatile("cp.async.commit_group;"); \
} while (0)

    LOAD_STAGE(0, 0);
    LOAD_STAGE(1, 1);
    LOAD_STAGE(2, 2);

    float acc[4][4][4];
#pragma unroll
    for (int i = 0; i < 4; i++)
#pragma unroll
        for (int j = 0; j < 4; j++)
#pragma unroll
            for (int k = 0; k < 4; k++) acc[i][j][k] = 0.0f;

    // ldmatrix lane mapping: group g=lane>>3 selects (row+8?, k+8?); j=lane&7 row
    const int g = lane >> 3, j = lane & 7;
    const uint32_t aoff = ((wm + j + (g & 1) * 8) * PADH + (g >> 1) * 8) * 2;
    const uint32_t boff = ((wn + j + (g & 1) * 8) * PADH + (g >> 1) * 8) * 2 + MAT_H * 2;

    for (int kc = 0; kc < 24; kc++) {
        asm volatile("cp.async.wait_group 2;");
        __syncthreads();
        const uint32_t base = sb + (uint32_t)(kc & 3) * STG_B;

#pragma unroll
        for (int s = 0; s < 2; s++) {
            const uint32_t k0b = s * 32;              // 16 halves
            uint32_t bf[4][2];
            ldsm4(bf[0][0], bf[1][0], bf[0][1], bf[1][1], base + boff + k0b);
            ldsm4(bf[2][0], bf[3][0], bf[2][1], bf[3][1],
                  base + boff + 16 * PADH * 2 + k0b);
#pragma unroll
            for (int mt = 0; mt < 4; mt++) {
                uint32_t af[4];
                ldsm4(af[0], af[1], af[2], af[3],
                      base + aoff + mt * 16 * PADH * 2 + k0b);
#pragma unroll
                for (int nt = 0; nt < 4; nt++)
                    mma_f16(acc[mt][nt], af, bf[nt]);
            }
        }
        if (kc + 3 < 24) {
            LOAD_STAGE((kc + 3) & 3, kc + 3);
        } else {
            asm volatile("cp.async.commit_group;");
        }
    }

    // epilogue: bias add + row-major fp32 store
    const int r = lane >> 2, q = lane & 3;
#pragma unroll
    for (int mt = 0; mt < 4; mt++) {
        const int row = m0 + wm + mt * 16 + r;
#pragma unroll
        for (int nt = 0; nt < 4; nt++) {
            const int col = n0 + wn + nt * 8 + 2 * q;
            const float b0 = bias[col], b1 = bias[col + 1];
            *(float2*)&C[(size_t)row * E + col] =
                make_float2(acc[mt][nt][0] + b0, acc[mt][nt][1] + b1);
            *(float2*)&C[(size_t)(row + 8) * E + col] =
                make_float2(acc[mt][nt][2] + b0, acc[mt][nt][3] + b1);
        }
    }
#undef LOAD_STAGE
}

// ---------------------------------------------------------------------------
// Normalize + transpose mapper matrices.
// ---------------------------------------------------------------------------
__global__ void norm_map(const float* __restrict__ qm, const float* __restrict__ xm,
                         float* __restrict__ qmT, float* __restrict__ xmT)
{
    int row  = blockIdx.x * (blockDim.x >> 5) + (threadIdx.x >> 5);
    int lane = threadIdx.x & 31;
    if (row < NT) {
        const float* x = qm + row * NQ;
        float ss = 0.0f;
        for (int i = lane; i < NQ; i += 32) { float v = x[i]; ss += v * v; }
#pragma unroll
        for (int o = 16; o; o >>= 1) ss += __shfl_xor_sync(0xffffffffu, ss, o);
        float s = 1.0f / fmaxf(sqrtf(ss), 1e-12f);
        for (int i = lane; i < NQ; i += 32) qmT[i * NT + row] = x[i] * s;
    } else if (row < NT + NQ) {
        int r = row - NT;
        const float* x = xm + r * NT;
        float ss = 0.0f;
        for (int i = lane; i < NT; i += 32) { float v = x[i]; ss += v * v; }
#pragma unroll
        for (int o = 16; o; o >>= 1) ss += __shfl_xor_sync(0xffffffffu, ss, o);
        float s = 1.0f / fmaxf(sqrtf(ss), 1e-12f);
        for (int i = lane; i < NT; i += 32) xmT[i * NQ + r] = x[i] * s;
    }
}

// ---------------------------------------------------------------------------
// Fused per-(b,h) attention with in-SMEM q/k L2 normalization.
// q/k/v row-major fp32 [tok*BSZ+b][E]; writes y as fp16.
// ---------------------------------------------------------------------------
#define SQP 101
#define SKP 197
#define SAP 65
#define ATTN_SMEM_FLOATS (64*SQP + 64*SKP + 64*SKP + 64*SAP)   // 35840
#define ROWSTR ((size_t)BSZ * E)

__global__ __launch_bounds__(512, 1)
void attn_kernel(const float* __restrict__ q_t, const float* __restrict__ k_t,
                 const float* __restrict__ v_t, const float* __restrict__ qmT,
                 const float* __restrict__ xmT, const float* __restrict__ temp,
                 __half* __restrict__ y)
{
    extern __shared__ float sm[];
    float* sQ = sm;
    float* sK = sQ + 64 * SQP;
    float* sM = sK + 64 * SKP;
    float* sA = sM + 64 * SKP;

    const int bh = blockIdx.x;
    const int b  = bh / NH;
    const int h  = bh % NH;
    const float* qp = q_t + (size_t)b * E + h * HD;
    const float* kp = k_t + (size_t)b * E + h * HD;
    const float* vp = v_t + (size_t)b * E + h * HD;

    const int tid  = threadIdx.x;
    const int w    = tid >> 5;
    const int lane = tid & 31;

    // Phase 0: gather q and k tiles
    for (int i = tid; i < NQ * 64; i += 512) {
        int tok = i >> 6, d = i & 63;
        sQ[d * SQP + tok] = qp[(size_t)tok * ROWSTR + d];
    }
    for (int i = tid; i < NT * 64; i += 512) {
        int tok = i >> 6, d = i & 63;
        sK[d * SKP + tok] = kp[(size_t)tok * ROWSTR + d];
    }
    __syncthreads();

    // Phase 0.5: fused L2 normalization over tokens
    for (int rr = w; rr < 128; rr += 16) {
        float* x; int L;
        if (rr < 64) { x = sQ + rr * SQP; L = NQ; }
        else         { x = sK + (rr - 64) * SKP; L = NT; }
        float ss = 0.0f;
        for (int i = lane; i < L; i += 32) { float v = x[i]; ss += v * v; }
#pragma unroll
        for (int o = 16; o; o >>= 1) ss += __shfl_xor_sync(0xffffffffu, ss, o);
        float sc = 1.0f / fmaxf(sqrtf(ss), 1e-12f);
        for (int i = lane; i < L; i += 32) x[i] *= sc;
    }
    __syncthreads();

    // Phase 1: qm[d,t] = sum_q sQ[d,q] * qmT[q,t]
    {
        const int d0 = (w >> 1) * 8;
        const int tb = lane + ((w & 1) << 5);
        for (int t = tb; t < NT; t += 64) {
            float acc[8] = {0,0,0,0,0,0,0,0};
            for (int qq = 0; qq < NQ; qq++) {
                float m = qmT[qq * NT + t];
#pragma unroll
                for (int i = 0; i < 8; i++)
                    acc[i] = fmaf(sQ[(d0 + i) * SQP + qq], m, acc[i]);
            }
#pragma unroll
            for (int i = 0; i < 8; i++) sM[(d0 + i) * SKP + t] = acc[i];
        }
    }
    __syncthreads();

    // Phase 2: attn[d,e] = temp[h] * sum_t qm[d,t] * kn[e,t]
    {
        const float tval = temp[h];
        const int e0 = (tid & 15) << 2;
        const int d0 = (tid >> 4) << 1;
        float acc[2][4] = {{0,0,0,0},{0,0,0,0}};
        for (int t = 0; t < NT; t++) {
            float a0 = sM[d0 * SKP + t];
            float a1 = sM[(d0 + 1) * SKP + t];
            float bv[4];
#pragma unroll
            for (int jj = 0; jj < 4; jj++) bv[jj] = sK[(e0 + jj) * SKP + t];
#pragma unroll
            for (int jj = 0; jj < 4; jj++) {
                acc[0][jj] = fmaf(a0, bv[jj], acc[0][jj]);
                acc[1][jj] = fmaf(a1, bv[jj], acc[1][jj]);
            }
        }
#pragma unroll
        for (int i = 0; i < 2; i++)
#pragma unroll
            for (int jj = 0; jj < 4; jj++)
                sA[(d0 + i) * SAP + e0 + jj] = acc[i][jj] * tval;
    }
    __syncthreads();

    // Phase 3: softmax rows (threads 0..63) while others gather v into sK
    if (tid < 64) {
        float* rr = sA + tid * SAP;
        float mx = rr[0];
#pragma unroll 8
        for (int e = 1; e < 64; e++) mx = fmaxf(mx, rr[e]);
        float s = 0.0f;
        for (int e = 0; e < 64; e++) { float ev = expf(rr[e] - mx); rr[e] = ev; s += ev; }
        float inv = 1.0f / s;
        for (int e = 0; e < 64; e++) rr[e] *= inv;
    } else {
        for (int i = tid - 64; i < NT * 64; i += 448) {
            int tok = i >> 6, d = i & 63;
            sK[d * SKP + tok] = vp[(size_t)tok * ROWSTR + d];
        }
    }
    __syncthreads();

    // Phase 4: x[d,t] = sum_e attn[d,e] * v[e,t] -> overwrite sM
    {
        const int d0 = (w >> 1) * 8;
        const int tb = lane + ((w & 1) << 5);
        for (int t = tb; t < NT; t += 64) {
            float acc[8] = {0,0,0,0,0,0,0,0};
            for (int e = 0; e < 64; e++) {
                float vv = sK[e * SKP + t];
#pragma unroll
                for (int i = 0; i < 8; i++)
                    acc[i] = fmaf(sA[(d0 + i) * SAP + e], vv, acc[i]);
            }
#pragma unroll
            for (int i = 0; i < 8; i++) sM[(d0 + i) * SKP + t] = acc[i];
        }
    }
    __syncthreads();

    // Phase 5: out[d,q] = sum_t x[d,t] * xmT[t,q]; write fp16 y
    {
        const int q0 = w * 8;
        if (q0 < NQ) {
            const int qlim = NQ - q0;
            const int d = lane;
            float acc0[8] = {0,0,0,0,0,0,0,0};
            float acc1[8] = {0,0,0,0,0,0,0,0};
            for (int t = 0; t < NT; t++) {
                float x0 = sM[d * SKP + t];
                float x1 = sM[(d + 32) * SKP + t];
#pragma unroll
                for (int jj = 0; jj < 8; jj++) {
                    float xv = (jj < qlim) ? xmT[t * NQ + q0 + jj] : 0.0f;
                    acc0[jj] = fmaf(x0, xv, acc0[jj]);
                    acc1[jj] = fmaf(x1, xv, acc1[jj]);
                }
            }
#pragma unroll
            for (int jj = 0; jj < 8; jj++) {
                if (jj < qlim) {
                    size_t base = ((size_t)(q0 + jj) * BSZ + b) * E + h * HD;
                    y[base + d]      = __float2half(acc0[jj]);
                    y[base + d + 32] = __float2half(acc1[jj]);
                }
            }
        }
    }
}

// ---------------------------------------------------------------------------
// Launch
// ---------------------------------------------------------------------------
extern "C" void kernel_launch(void* const* d_in, const int* in_sizes, int n_in,
                              void* d_out, int out_size)
{
    const float* query = (const float*)d_in[0];
    const float* key   = (const float*)d_in[1];
    const float* value = (const float*)d_in[2];
    const float* ipw   = (const float*)d_in[3];
    const float* ipb   = (const float*)d_in[4];
    const float* opw   = (const float*)d_in[5];
    const float* opb   = (const float*)d_in[6];
    const float* temp  = (const float*)d_in[7];
    const float* qmap  = (const float*)d_in[8];
    const float* xmap  = (const float*)d_in[9];
    float* out = (float*)d_out;

    float *qt, *kt, *vt, *qmT, *xmT;
    __half *qh, *kh, *vh, *wh, *owh, *yh;
    cudaGetSymbolAddress((void**)&qt,  g_qt);
    cudaGetSymbolAddress((void**)&kt,  g_kt);
    cudaGetSymbolAddress((void**)&vt,  g_vt);
    cudaGetSymbolAddress((void**)&qmT, g_qmT);
    cudaGetSymbolAddress((void**)&xmT, g_xmT);
    cudaGetSymbolAddress((void**)&qh,  g_qh);
    cudaGetSymbolAddress((void**)&kh,  g_kh);
    cudaGetSymbolAddress((void**)&vh,  g_vh);
    cudaGetSymbolAddress((void**)&wh,  g_wh);
    cudaGetSymbolAddress((void**)&owh, g_owh);
    cudaGetSymbolAddress((void**)&yh,  g_yh);

    cudaFuncSetAttribute(gemm_h, cudaFuncAttributeMaxDynamicSharedMemorySize, GEMM_SMEM);
    cudaFuncSetAttribute(attn_kernel, cudaFuncAttributeMaxDynamicSharedMemorySize,
                         ATTN_SMEM_FLOATS * sizeof(float));

    // 0) fp32 -> fp16 conversions (inputs + weights)
    auto conv = [](const float* src, __half* dst, int n) {
        int n4 = n / 4;
        f2h<<<(n4 + 255) / 256, 256>>>((const float4*)src, (__half2*)dst, n4);
    };
    conv(query, qh, NQ * BSZ * E);
    conv(key,   kh, NT * BSZ * E);
    conv(value, vh, NT * BSZ * E);
    conv(ipw,   wh, 3 * E * E);
    conv(opw,   owh, E * E);

    // 1) Projections (fp16 mma.sync + ldmatrix), fp32 row-major outputs
    dim3 gq(6, (NQ * BSZ) / 128);   // (6, 100)
    dim3 gk(6, (NT * BSZ) / 128);   // (6, 197)
    gemm_h<<<gq, 256, GEMM_SMEM>>>(qh, wh,             ipb,         qt);
    gemm_h<<<gk, 256, GEMM_SMEM>>>(kh, wh + E * E,     ipb + E,     kt);
    gemm_h<<<gk, 256, GEMM_SMEM>>>(vh, wh + 2 * E * E, ipb + 2 * E, vt);

    // 2) Normalize + transpose mapper matrices
    norm_map<<<(NT + NQ + 7) / 8, 256>>>(qmap, xmap, qmT, xmT);

    // 3) Fused attention per (b,h) (includes q/k L2 norm), fp16 y out
    attn_kernel<<<BH, 512, ATTN_SMEM_FLOATS * sizeof(float)>>>(qt, kt, vt, qmT, xmT, temp, yh);

    // 4) Output projection -> d_out (fp32)
    gemm_h<<<gq, 256, GEMM_SMEM>>>(yh, owh, opb, out);
}

// round 8
// speedup vs baseline: 2.3577x; 1.7421x over previous
#include <cuda_runtime.h>
#include <cuda_fp16.h>
#include <math.h>
#include <cstdint>

// Problem constants
#define NQ   100
#define NT   197
#define BSZ  128
#define E    768
#define NH   12
#define HD   64
#define BH   (BSZ*NH)          // 1536
#define ROWSTR ((size_t)BSZ * E)

// ---------------------------------------------------------------------------
// Device scratch
// ---------------------------------------------------------------------------
__device__ float  g_qt[NQ * BSZ * E];      // fp32 GEMM outputs (attn inputs)
__device__ float  g_kt[NT * BSZ * E];
__device__ float  g_vt[NT * BSZ * E];
__device__ __half g_qh[NQ * BSZ * E];      // fp16 GEMM inputs
__device__ __half g_kh[NT * BSZ * E];
__device__ __half g_vh[NT * BSZ * E];
__device__ __half g_wh[3 * E * E];
__device__ __half g_owh[E * E];
__device__ __half g_yh[NQ * BSZ * E];      // fp16 attention output
__device__ __half g_qmH[256 * 112];        // normalized q_mapper fp16 [t][q], zero-padded
__device__ __half g_xmH[128 * 256];        // normalized x_mapper fp16 [q][t], zero-padded

// ---------------------------------------------------------------------------
// Common PTX helpers
// ---------------------------------------------------------------------------
__device__ __forceinline__ uint32_t smem_u32(const void* p) {
    uint32_t a;
    asm("{ .reg .u64 t; cvta.to.shared.u64 t, %1; cvt.u32.u64 %0, t; }"
        : "=r"(a) : "l"(p));
    return a;
}
__device__ __forceinline__ void cpa16(uint32_t dst, const void* src) {
    asm volatile("cp.async.cg.shared.global [%0], [%1], 16;" :: "r"(dst), "l"(src));
}
__device__ __forceinline__ void ldsm4(uint32_t& r0, uint32_t& r1, uint32_t& r2,
                                      uint32_t& r3, uint32_t addr) {
    asm volatile("ldmatrix.sync.aligned.m8n8.x4.shared.b16 {%0,%1,%2,%3}, [%4];"
                 : "=r"(r0), "=r"(r1), "=r"(r2), "=r"(r3) : "r"(addr));
}
__device__ __forceinline__ void mma_f16(float* c, const uint32_t* a, const uint32_t* b) {
    asm volatile(
        "mma.sync.aligned.m16n8k16.row.col.f32.f16.f16.f32 "
        "{%0,%1,%2,%3}, {%4,%5,%6,%7}, {%8,%9}, {%0,%1,%2,%3};"
        : "+f"(c[0]), "+f"(c[1]), "+f"(c[2]), "+f"(c[3])
        : "r"(a[0]), "r"(a[1]), "r"(a[2]), "r"(a[3]), "r"(b[0]), "r"(b[1]));
}

// ---------------------------------------------------------------------------
// fp32 -> fp16 conversion
// ---------------------------------------------------------------------------
__global__ void f2h(const float4* __restrict__ in, __half2* __restrict__ out, int n4)
{
    int i = blockIdx.x * blockDim.x + threadIdx.x;
    if (i < n4) {
        float4 v = in[i];
        out[2 * i]     = __floats2half2_rn(v.x, v.y);
        out[2 * i + 1] = __floats2half2_rn(v.z, v.w);
    }
}

// ---------------------------------------------------------------------------
// fp16 mma.sync GEMM (unchanged from round 7 — known good)
// ---------------------------------------------------------------------------
#define PADH      40
#define MAT_H     (128 * PADH)
#define STG_B     (2 * MAT_H * 2)
#define GEMM_SMEM (4 * STG_B)

__global__ __launch_bounds__(256, 2)
void gemm_h(const __half* __restrict__ A, const __half* __restrict__ W,
            const float* __restrict__ bias, float* __restrict__ C)
{
    extern __shared__ __half smh[];
    const uint32_t sb = smem_u32(smh);
    const int tid  = threadIdx.x;
    const int lane = tid & 31;
    const int wid  = tid >> 5;
    const int m0 = blockIdx.y * 128, n0 = blockIdx.x * 128;
    const int wm = (wid >> 2) * 64;
    const int wn = (wid & 3) * 32;

    const int prow = tid >> 1;
    const int pseg = (tid & 1) * 16;
    const __half* gA = A + (size_t)(m0 + prow) * E + pseg;
    const __half* gB = W + (size_t)(n0 + prow) * E + pseg;
    const uint32_t sAa = sb + (prow * PADH + pseg) * 2;
    const uint32_t sBa = sAa + MAT_H * 2;

#define LOAD_STAGE(st, kc) do { \
    const uint32_t so = (uint32_t)(st) * STG_B; \
    const __half* ga = gA + (kc) * 32; \
    const __half* gb = gB + (kc) * 32; \
    cpa16(sAa + so,      ga);     cpa16(sAa + so + 16, ga + 8); \
    cpa16(sBa + so,      gb);     cpa16(sBa + so + 16, gb + 8); \
    asm volatile("cp.async.commit_group;"); \
} while (0)

    LOAD_STAGE(0, 0);
    LOAD_STAGE(1, 1);
    LOAD_STAGE(2, 2);

    float acc[4][4][4];
#pragma unroll
    for (int i = 0; i < 4; i++)
#pragma unroll
        for (int j = 0; j < 4; j++)
#pragma unroll
            for (int k = 0; k < 4; k++) acc[i][j][k] = 0.0f;

    const int g = lane >> 3, j = lane & 7;
    const uint32_t aoff = ((wm + j + (g & 1) * 8) * PADH + (g >> 1) * 8) * 2;
    const uint32_t boff = ((wn + j + (g & 1) * 8) * PADH + (g >> 1) * 8) * 2 + MAT_H * 2;

    for (int kc = 0; kc < 24; kc++) {
        asm volatile("cp.async.wait_group 2;");
        __syncthreads();
        const uint32_t base = sb + (uint32_t)(kc & 3) * STG_B;

#pragma unroll
        for (int s = 0; s < 2; s++) {
            const uint32_t k0b = s * 32;
            uint32_t bf[4][2];
            ldsm4(bf[0][0], bf[1][0], bf[0][1], bf[1][1], base + boff + k0b);
            ldsm4(bf[2][0], bf[3][0], bf[2][1], bf[3][1],
                  base + boff + 16 * PADH * 2 + k0b);
#pragma unroll
            for (int mt = 0; mt < 4; mt++) {
                uint32_t af[4];
                ldsm4(af[0], af[1], af[2], af[3],
                      base + aoff + mt * 16 * PADH * 2 + k0b);
#pragma unroll
                for (int nt = 0; nt < 4; nt++)
                    mma_f16(acc[mt][nt], af, bf[nt]);
            }
        }
        if (kc + 3 < 24) {
            LOAD_STAGE((kc + 3) & 3, kc + 3);
        } else {
            asm volatile("cp.async.commit_group;");
        }
    }

    const int r = lane >> 2, q = lane & 3;
#pragma unroll
    for (int mt = 0; mt < 4; mt++) {
        const int row = m0 + wm + mt * 16 + r;
#pragma unroll
        for (int nt = 0; nt < 4; nt++) {
            const int col = n0 + wn + nt * 8 + 2 * q;
            const float b0 = bias[col], b1 = bias[col + 1];
            *(float2*)&C[(size_t)row * E + col] =
                make_float2(acc[mt][nt][0] + b0, acc[mt][nt][1] + b1);
            *(float2*)&C[(size_t)(row + 8) * E + col] =
                make_float2(acc[mt][nt][2] + b0, acc[mt][nt][3] + b1);
        }
    }
#undef LOAD_STAGE
}

// ---------------------------------------------------------------------------
// Normalize mapper matrices -> zero-padded fp16 (qmH [256][112], xmH [128][256])
// ---------------------------------------------------------------------------
__global__ void norm_map_h(const float* __restrict__ qm, const float* __restrict__ xm,
                           __half* __restrict__ qmH, __half* __restrict__ xmH)
{
    int row  = blockIdx.x * (blockDim.x >> 5) + (threadIdx.x >> 5);
    int lane = threadIdx.x & 31;
    const __half hz = __float2half(0.0f);
    if (row < 256) {
        __half* dst = qmH + row * 112;
        if (row < NT) {
            const float* x = qm + row * NQ;
            float ss = 0.0f;
            for (int i = lane; i < NQ; i += 32) { float v = x[i]; ss += v * v; }
#pragma unroll
            for (int o = 16; o; o >>= 1) ss += __shfl_xor_sync(0xffffffffu, ss, o);
            float s = 1.0f / fmaxf(sqrtf(ss), 1e-12f);
            for (int i = lane; i < 112; i += 32)
                dst[i] = (i < NQ) ? __float2half(x[i] * s) : hz;
        } else {
            for (int i = lane; i < 112; i += 32) dst[i] = hz;
        }
    } else if (row < 384) {
        int r = row - 256;
        __half* dst = xmH + r * 256;
        if (r < NQ) {
            const float* x = xm + r * NT;
            float ss = 0.0f;
            for (int i = lane; i < NT; i += 32) { float v = x[i]; ss += v * v; }
#pragma unroll
            for (int o = 16; o; o >>= 1) ss += __shfl_xor_sync(0xffffffffu, ss, o);
            float s = 1.0f / fmaxf(sqrtf(ss), 1e-12f);
            for (int i = lane; i < 256; i += 32)
                dst[i] = (i < NT) ? __float2half(x[i] * s) : hz;
        } else {
            for (int i = lane; i < 256; i += 32) dst[i] = hz;
        }
    }
}

// ---------------------------------------------------------------------------
// Tensor-core fused attention. One CTA per (b,h), 512 threads (16 warps).
// All 4 matmul phases via m16n8k16 fp16 MMA, fp32 accumulate.
//   P1: qm[64,256]  = qn[64,112]  @ qmH[256,112]^T(B)     (LDG B-frags)
//   P2: S [64,64]   = qm[64,256]  @ kn[64,256]^T(B)       (ldsm B)
//   P4: x [64,256]  = P [64,64]   @ hV[256,64]^T(B)       (ldsm B)
//   P5: out[64,128] = x [64,256]  @ xmH[128,256]^T(B)     (LDG B-frags)
// ---------------------------------------------------------------------------
#define HQ_S 120
#define HK_S 264
#define HV_S 72
#define HP_S 72
#define SS_S 66
#define SO_S 68
#define OFF_HQ 0
#define OFF_HK 7680
#define OFF_HM 24576
#define OFF_HV 41472
#define OFF_HP 59904
#define OFF_SS 64512
#define ATTN_SMEM_BYTES ((64512 + 8448) * 2)   // 145920

__global__ __launch_bounds__(512, 1)
void attn_tc(const float* __restrict__ q_t, const float* __restrict__ k_t,
             const float* __restrict__ v_t, const __half* __restrict__ qmH,
             const __half* __restrict__ xmH, const float* __restrict__ temp,
             __half* __restrict__ y)
{
    extern __shared__ __half sh[];
    __half* hQ = sh + OFF_HQ;
    __half* hK = sh + OFF_HK;
    __half* hM = sh + OFF_HM;
    __half* hV = sh + OFF_HV;
    __half* hP = sh + OFF_HP;
    float*  sS = (float*)(sh + OFF_SS);
    float*  sOut = (float*)(sh + OFF_HV);     // reuse hV region after P4
    const uint32_t sbase = smem_u32(sh);

    const int bh = blockIdx.x;
    const int b  = bh / NH;
    const int h  = bh % NH;
    const float* qp = q_t + (size_t)b * E + h * HD;
    const float* kp = k_t + (size_t)b * E + h * HD;
    const float* vp = v_t + (size_t)b * E + h * HD;

    const int tid  = threadIdx.x;
    const int wid  = tid >> 5;
    const int lane = tid & 31;
    const int g    = lane >> 3;
    const int jj   = lane & 7;
    const int r    = lane >> 2;
    const int qq   = lane & 3;

    // ---- zero hQ+hK and hV regions (padding correctness) ----
    {
        uint32_t* z1 = (uint32_t*)sh;                 // hQ+hK: 24576 halves
        for (int i = tid; i < 24576 / 2; i += 512) z1[i] = 0u;
        uint32_t* z2 = (uint32_t*)(sh + OFF_HV);      // hV: 18432 halves
        for (int i = tid; i < 18432 / 2; i += 512) z2[i] = 0u;
    }
    __syncthreads();

    // ---- load q,k (transposed to channel-major fp16), v (natural rows) ----
    for (int i = tid; i < NQ * 32; i += 512) {
        int tok = i >> 5, c = i & 31;
        float2 v2 = *(const float2*)(qp + (size_t)tok * ROWSTR + 2 * c);
        hQ[(2 * c) * HQ_S + tok]     = __float2half(v2.x);
        hQ[(2 * c + 1) * HQ_S + tok] = __float2half(v2.y);
    }
    for (int i = tid; i < NT * 32; i += 512) {
        int tok = i >> 5, c = i & 31;
        float2 v2 = *(const float2*)(kp + (size_t)tok * ROWSTR + 2 * c);
        hK[(2 * c) * HK_S + tok]     = __float2half(v2.x);
        hK[(2 * c + 1) * HK_S + tok] = __float2half(v2.y);
    }
    for (int i = tid; i < NT * 32; i += 512) {
        int tok = i >> 5, c = i & 31;
        float2 v2 = *(const float2*)(vp + (size_t)tok * ROWSTR + 2 * c);
        *(__half2*)&hV[tok * HV_S + 2 * c] = __floats2half2_rn(v2.x, v2.y);
    }
    __syncthreads();

    // ---- L2 norms (in fp16 SMEM, fp32 math) ----
    for (int rr = wid; rr < 128; rr += 16) {
        __half2* x; int nh2;
        if (rr < 64) { x = (__half2*)(hQ + rr * HQ_S); nh2 = 50; }
        else         { x = (__half2*)(hK + (rr - 64) * HK_S); nh2 = 100; }
        float ss = 0.0f;
        for (int i = lane; i < nh2; i += 32) {
            float2 f = __half22float2(x[i]);
            ss += f.x * f.x + f.y * f.y;
        }
#pragma unroll
        for (int o = 16; o; o >>= 1) ss += __shfl_xor_sync(0xffffffffu, ss, o);
        float sc = 1.0f / fmaxf(sqrtf(ss), 1e-12f);
        for (int i = lane; i < nh2; i += 32) {
            float2 f = __half22float2(x[i]);
            x[i] = __floats2half2_rn(f.x * sc, f.y * sc);
        }
    }
    __syncthreads();

    // ---- P1: qm[64,256] = qn @ qmH^T, write hM fp16 ----
    {
        const int mb = (wid & 3) * 16;
        const int nb = (wid >> 2) * 64;
        const uint32_t aBase = sbase +
            (OFF_HQ + (mb + jj + (g & 1) * 8) * HQ_S + (g >> 1) * 8) * 2;
        float acc[8][4];
#pragma unroll
        for (int i = 0; i < 8; i++)
#pragma unroll
            for (int k = 0; k < 4; k++) acc[i][k] = 0.0f;
        const int k0l = 2 * qq;
#pragma unroll
        for (int kk = 0; kk < 7; kk++) {
            uint32_t af[4];
            ldsm4(af[0], af[1], af[2], af[3], aBase + kk * 32);
#pragma unroll
            for (int nb8 = 0; nb8 < 8; nb8++) {
                const __half* bp = qmH + (nb + nb8 * 8 + r) * 112 + kk * 16 + k0l;
                uint32_t bf[2];
                bf[0] = *(const uint32_t*)bp;
                bf[1] = *(const uint32_t*)(bp + 8);
                mma_f16(acc[nb8], af, bf);
            }
        }
#pragma unroll
        for (int nb8 = 0; nb8 < 8; nb8++) {
            int col = nb + nb8 * 8 + 2 * qq;
            *(__half2*)&hM[(mb + r) * HK_S + col]     = __floats2half2_rn(acc[nb8][0], acc[nb8][1]);
            *(__half2*)&hM[(mb + r + 8) * HK_S + col] = __floats2half2_rn(acc[nb8][2], acc[nb8][3]);
        }
    }
    __syncthreads();

    // ---- P2: S[64,64] = qm @ kn^T, write sS fp32 (with temp scale) ----
    {
        const int mb = (wid & 3) * 16;
        const int nb = (wid >> 2) * 16;
        const uint32_t aBase = sbase +
            (OFF_HM + (mb + jj + (g & 1) * 8) * HK_S + (g >> 1) * 8) * 2;
        const uint32_t bBase = sbase +
            (OFF_HK + (nb + jj + (g & 1) * 8) * HK_S + (g >> 1) * 8) * 2;
        float acc[2][4];
#pragma unroll
        for (int i = 0; i < 2; i++)
#pragma unroll
            for (int k = 0; k < 4; k++) acc[i][k] = 0.0f;
#pragma unroll
        for (int kk = 0; kk < 16; kk++) {
            uint32_t af[4], b0, b1, b2, b3;
            ldsm4(af[0], af[1], af[2], af[3], aBase + kk * 32);
            ldsm4(b0, b1, b2, b3, bBase + kk * 32);
            uint32_t bfA[2] = {b0, b2}, bfB[2] = {b1, b3};
            mma_f16(acc[0], af, bfA);
            mma_f16(acc[1], af, bfB);
        }
        const float tval = temp[h];
#pragma unroll
        for (int t = 0; t < 2; t++) {
            int col = nb + t * 8 + 2 * qq;
            sS[(mb + r) * SS_S + col]         = acc[t][0] * tval;
            sS[(mb + r) * SS_S + col + 1]     = acc[t][1] * tval;
            sS[(mb + r + 8) * SS_S + col]     = acc[t][2] * tval;
            sS[(mb + r + 8) * SS_S + col + 1] = acc[t][3] * tval;
        }
    }
    __syncthreads();

    // ---- softmax rows of sS -> hP fp16 ----
    if (tid < 64) {
        float* rw = sS + tid * SS_S;
        float mx = rw[0];
#pragma unroll 8
        for (int e = 1; e < 64; e++) mx = fmaxf(mx, rw[e]);
        float s = 0.0f;
        for (int e = 0; e < 64; e++) { float ev = __expf(rw[e] - mx); rw[e] = ev; s += ev; }
        float inv = 1.0f / s;
        __half* pp = hP + tid * HP_S;
        for (int e = 0; e < 64; e++) pp[e] = __float2half(rw[e] * inv);
    }
    __syncthreads();

    // ---- P4: x[64,256] = P @ hV^T, overwrite hM fp16 ----
    {
        const int mb = (wid & 3) * 16;
        const int nb = (wid >> 2) * 64;
        const uint32_t aBase = sbase +
            (OFF_HP + (mb + jj + (g & 1) * 8) * HP_S + (g >> 1) * 8) * 2;
        uint32_t bBase[4];
#pragma unroll
        for (int nt = 0; nt < 4; nt++)
            bBase[nt] = sbase +
                (OFF_HV + (nb + nt * 16 + jj + (g & 1) * 8) * HV_S + (g >> 1) * 8) * 2;
        float acc[8][4];
#pragma unroll
        for (int i = 0; i < 8; i++)
#pragma unroll
            for (int k = 0; k < 4; k++) acc[i][k] = 0.0f;
#pragma unroll
        for (int kk = 0; kk < 4; kk++) {
            uint32_t af[4];
            ldsm4(af[0], af[1], af[2], af[3], aBase + kk * 32);
#pragma unroll
            for (int nt = 0; nt < 4; nt++) {
                uint32_t b0, b1, b2, b3;
                ldsm4(b0, b1, b2, b3, bBase[nt] + kk * 32);
                uint32_t bfA[2] = {b0, b2}, bfB[2] = {b1, b3};
                mma_f16(acc[nt * 2], af, bfA);
                mma_f16(acc[nt * 2 + 1], af, bfB);
            }
        }
#pragma unroll
        for (int nb8 = 0; nb8 < 8; nb8++) {
            int col = nb + nb8 * 8 + 2 * qq;
            *(__half2*)&hM[(mb + r) * HK_S + col]     = __floats2half2_rn(acc[nb8][0], acc[nb8][1]);
            *(__half2*)&hM[(mb + r + 8) * HK_S + col] = __floats2half2_rn(acc[nb8][2], acc[nb8][3]);
        }
    }
    __syncthreads();

    // ---- P5: out[64,128] = x @ xmH^T, write sOut fp32 transposed [q][d] ----
    {
        const int mb = (wid & 3) * 16;
        const int nb = (wid >> 2) * 32;
        const uint32_t aBase = sbase +
            (OFF_HM + (mb + jj + (g & 1) * 8) * HK_S + (g >> 1) * 8) * 2;
        float acc[4][4];
#pragma unroll
        for (int i = 0; i < 4; i++)
#pragma unroll
            for (int k = 0; k < 4; k++) acc[i][k] = 0.0f;
        const int k0l = 2 * qq;
#pragma unroll
        for (int kk = 0; kk < 16; kk++) {
            uint32_t af[4];
            ldsm4(af[0], af[1], af[2], af[3], aBase + kk * 32);
#pragma unroll
            for (int nb8 = 0; nb8 < 4; nb8++) {
                const __half* bp = xmH + (nb + nb8 * 8 + r) * 256 + kk * 16 + k0l;
                uint32_t bf[2];
                bf[0] = *(const uint32_t*)bp;
                bf[1] = *(const uint32_t*)(bp + 8);
                mma_f16(acc[nb8], af, bf);
            }
        }
        __syncthreads();   // all reads of hV-region (P4 B) done before sOut overwrite
#pragma unroll
        for (int nb8 = 0; nb8 < 4; nb8++) {
            int q0 = nb + nb8 * 8 + 2 * qq;
            int d0 = mb + r;
            sOut[q0 * SO_S + d0]           = acc[nb8][0];
            sOut[(q0 + 1) * SO_S + d0]     = acc[nb8][1];
            sOut[q0 * SO_S + d0 + 8]       = acc[nb8][2];
            sOut[(q0 + 1) * SO_S + d0 + 8] = acc[nb8][3];
        }
    }
    __syncthreads();

    // ---- epilogue: coalesced fp16 store of q<100 rows ----
    for (int i = tid; i < NQ * 32; i += 512) {
        int q = i >> 5, c = i & 31;
        float a0 = sOut[q * SO_S + 2 * c];
        float a1 = sOut[q * SO_S + 2 * c + 1];
        *(__half2*)&y[((size_t)q * BSZ + b) * E + h * HD + 2 * c] =
            __floats2half2_rn(a0, a1);
    }
}

// ---------------------------------------------------------------------------
// Launch (ordered so gemm_h is the 4th launch -> gets profiled)
// ---------------------------------------------------------------------------
extern "C" void kernel_launch(void* const* d_in, const int* in_sizes, int n_in,
                              void* d_out, int out_size)
{
    const float* query = (const float*)d_in[0];
    const float* key   = (const float*)d_in[1];
    const float* value = (const float*)d_in[2];
    const float* ipw   = (const float*)d_in[3];
    const float* ipb   = (const float*)d_in[4];
    const float* opw   = (const float*)d_in[5];
    const float* opb   = (const float*)d_in[6];
    const float* temp  = (const float*)d_in[7];
    const float* qmap  = (const float*)d_in[8];
    const float* xmap  = (const float*)d_in[9];
    float* out = (float*)d_out;

    float *qt, *kt, *vt;
    __half *qh, *kh, *vh, *wh, *owh, *yh, *qmH, *xmH;
    cudaGetSymbolAddress((void**)&qt,  g_qt);
    cudaGetSymbolAddress((void**)&kt,  g_kt);
    cudaGetSymbolAddress((void**)&vt,  g_vt);
    cudaGetSymbolAddress((void**)&qh,  g_qh);
    cudaGetSymbolAddress((void**)&kh,  g_kh);
    cudaGetSymbolAddress((void**)&vh,  g_vh);
    cudaGetSymbolAddress((void**)&wh,  g_wh);
    cudaGetSymbolAddress((void**)&owh, g_owh);
    cudaGetSymbolAddress((void**)&yh,  g_yh);
    cudaGetSymbolAddress((void**)&qmH, g_qmH);
    cudaGetSymbolAddress((void**)&xmH, g_xmH);

    cudaFuncSetAttribute(gemm_h, cudaFuncAttributeMaxDynamicSharedMemorySize, GEMM_SMEM);
    cudaFuncSetAttribute(attn_tc, cudaFuncAttributeMaxDynamicSharedMemorySize,
                         ATTN_SMEM_BYTES);

    auto conv = [](const float* src, __half* dst, int n) {
        int n4 = n / 4;
        f2h<<<(n4 + 255) / 256, 256>>>((const float4*)src, (__half2*)dst, n4);
    };

    dim3 gq(6, (NQ * BSZ) / 128);
    dim3 gk(6, (NT * BSZ) / 128);

    // 1-3
    norm_map_h<<<48, 256>>>(qmap, xmap, qmH, xmH);
    conv(query, qh, NQ * BSZ * E);
    conv(ipw,   wh, 3 * E * E);
    // 4: gemm_h (profiled slot)
    gemm_h<<<gq, 256, GEMM_SMEM>>>(qh, wh, ipb, qt);
    // 5-7
    conv(key,   kh, NT * BSZ * E);
    conv(value, vh, NT * BSZ * E);
    conv(opw,   owh, E * E);
    // 8-9
    gemm_h<<<gk, 256, GEMM_SMEM>>>(kh, wh + E * E,     ipb + E,     kt);
    gemm_h<<<gk, 256, GEMM_SMEM>>>(vh, wh + 2 * E * E, ipb + 2 * E, vt);
    // 10: attention (tensor-core)
    attn_tc<<<BH, 512, ATTN_SMEM_BYTES>>>(qt, kt, vt, qmH, xmH, temp, yh);
    // 11: output projection
    gemm_h<<<gq, 256, GEMM_SMEM>>>(yh, owh, opb, out);
}

// round 13
// speedup vs baseline: 2.7623x; 1.1716x over previous
#include <cuda_runtime.h>
#include <cuda_fp16.h>
#include <math.h>
#include <cstdint>

// Problem constants
#define NQ   100
#define NT   197
#define BSZ  128
#define E    768
#define NH   12
#define HD   64
#define BH   (BSZ*NH)
#define ROWSTR ((size_t)BSZ * E)

// ---------------------------------------------------------------------------
// Device scratch
// ---------------------------------------------------------------------------
__device__ __half g_qh[NQ * BSZ * E];      // fp16 inputs to projections
__device__ __half g_kh[NT * BSZ * E];
__device__ __half g_vh[NT * BSZ * E];
__device__ __half g_wh[3 * E * E];
__device__ __half g_owh[E * E];
__device__ __half g_qph[NQ * BSZ * E];     // fp16 projection outputs
__device__ __half g_kph[NT * BSZ * E];
__device__ __half g_vph[NT * BSZ * E];
__device__ __half g_yh[NQ * BSZ * E];      // fp16 attention output
__device__ __half g_qmH[256 * 112];        // normalized q_mapper fp16 [t][q], zero-pad
__device__ __half g_xmH[128 * 256];        // normalized x_mapper fp16 [q][t], zero-pad

// ---------------------------------------------------------------------------
// Common PTX helpers
// ---------------------------------------------------------------------------
__device__ __forceinline__ uint32_t smem_u32(const void* p) {
    uint32_t a;
    asm("{ .reg .u64 t; cvta.to.shared.u64 t, %1; cvt.u32.u64 %0, t; }"
        : "=r"(a) : "l"(p));
    return a;
}
__device__ __forceinline__ void cpa16(uint32_t dst, const void* src) {
    asm volatile("cp.async.cg.shared.global [%0], [%1], 16;" :: "r"(dst), "l"(src));
}
__device__ __forceinline__ void ldsm4(uint32_t& r0, uint32_t& r1, uint32_t& r2,
                                      uint32_t& r3, uint32_t addr) {
    asm volatile("ldmatrix.sync.aligned.m8n8.x4.shared.b16 {%0,%1,%2,%3}, [%4];"
                 : "=r"(r0), "=r"(r1), "=r"(r2), "=r"(r3) : "r"(addr));
}
__device__ __forceinline__ void mma_f16(float* c, const uint32_t* a, const uint32_t* b) {
    asm volatile(
        "mma.sync.aligned.m16n8k16.row.col.f32.f16.f16.f32 "
        "{%0,%1,%2,%3}, {%4,%5,%6,%7}, {%8,%9}, {%0,%1,%2,%3};"
        : "+f"(c[0]), "+f"(c[1]), "+f"(c[2]), "+f"(c[3])
        : "r"(a[0]), "r"(a[1]), "r"(a[2]), "r"(a[3]), "r"(b[0]), "r"(b[1]));
}

// ---------------------------------------------------------------------------
// fp32 -> fp16 conversion
// ---------------------------------------------------------------------------
__global__ void f2h(const float4* __restrict__ in, __half2* __restrict__ out, int n4)
{
    int i = blockIdx.x * blockDim.x + threadIdx.x;
    if (i < n4) {
        float4 v = in[i];
        out[2 * i]     = __floats2half2_rn(v.x, v.y);
        out[2 * i + 1] = __floats2half2_rn(v.z, v.w);
    }
}

// ---------------------------------------------------------------------------
// fp16 mma.sync GEMM. OUTH=true -> fp16 output, else fp32.
// ---------------------------------------------------------------------------
#define PADH      40
#define MAT_H     (128 * PADH)
#define STG_B     (2 * MAT_H * 2)
#define GEMM_SMEM (4 * STG_B)

template<bool OUTH>
__global__ __launch_bounds__(256, 2)
void gemm_h(const __half* __restrict__ A, const __half* __restrict__ W,
            const float* __restrict__ bias, void* __restrict__ Cv)
{
    extern __shared__ __half smh[];
    const uint32_t sb = smem_u32(smh);
    const int tid  = threadIdx.x;
    const int lane = tid & 31;
    const int wid  = tid >> 5;
    const int m0 = blockIdx.y * 128, n0 = blockIdx.x * 128;
    const int wm = (wid >> 2) * 64;
    const int wn = (wid & 3) * 32;

    const int prow = tid >> 1;
    const int pseg = (tid & 1) * 16;
    const __half* gA = A + (size_t)(m0 + prow) * E + pseg;
    const __half* gB = W + (size_t)(n0 + prow) * E + pseg;
    const uint32_t sAa = sb + (prow * PADH + pseg) * 2;
    const uint32_t sBa = sAa + MAT_H * 2;

#define LOAD_STAGE(st, kc) do { \
    const uint32_t so = (uint32_t)(st) * STG_B; \
    const __half* ga = gA + (kc) * 32; \
    const __half* gb = gB + (kc) * 32; \
    cpa16(sAa + so,      ga);     cpa16(sAa + so + 16, ga + 8); \
    cpa16(sBa + so,      gb);     cpa16(sBa + so + 16, gb + 8); \
    asm volatile("cp.async.commit_group;"); \
} while (0)

    LOAD_STAGE(0, 0);
    LOAD_STAGE(1, 1);
    LOAD_STAGE(2, 2);

    float acc[4][4][4];
#pragma unroll
    for (int i = 0; i < 4; i++)
#pragma unroll
        for (int j = 0; j < 4; j++)
#pragma unroll
            for (int k = 0; k < 4; k++) acc[i][j][k] = 0.0f;

    const int g = lane >> 3, j = lane & 7;
    const uint32_t aoff = ((wm + j + (g & 1) * 8) * PADH + (g >> 1) * 8) * 2;
    const uint32_t boff = ((wn + j + (g & 1) * 8) * PADH + (g >> 1) * 8) * 2 + MAT_H * 2;

    for (int kc = 0; kc < 24; kc++) {
        asm volatile("cp.async.wait_group 2;");
        __syncthreads();
        const uint32_t base = sb + (uint32_t)(kc & 3) * STG_B;

#pragma unroll
        for (int s = 0; s < 2; s++) {
            const uint32_t k0b = s * 32;
            uint32_t bf[4][2];
            ldsm4(bf[0][0], bf[1][0], bf[0][1], bf[1][1], base + boff + k0b);
            ldsm4(bf[2][0], bf[3][0], bf[2][1], bf[3][1],
                  base + boff + 16 * PADH * 2 + k0b);
#pragma unroll
            for (int mt = 0; mt < 4; mt++) {
                uint32_t af[4];
                ldsm4(af[0], af[1], af[2], af[3],
                      base + aoff + mt * 16 * PADH * 2 + k0b);
#pragma unroll
                for (int nt = 0; nt < 4; nt++)
                    mma_f16(acc[mt][nt], af, bf[nt]);
            }
        }
        if (kc + 3 < 24) {
            LOAD_STAGE((kc + 3) & 3, kc + 3);
        } else {
            asm volatile("cp.async.commit_group;");
        }
    }

    const int r = lane >> 2, q = lane & 3;
#pragma unroll
    for (int mt = 0; mt < 4; mt++) {
        const int row = m0 + wm + mt * 16 + r;
#pragma unroll
        for (int nt = 0; nt < 4; nt++) {
            const int col = n0 + wn + nt * 8 + 2 * q;
            const float b0 = bias[col], b1 = bias[col + 1];
            if (OUTH) {
                __half* C = (__half*)Cv;
                *(__half2*)&C[(size_t)row * E + col] =
                    __floats2half2_rn(acc[mt][nt][0] + b0, acc[mt][nt][1] + b1);
                *(__half2*)&C[(size_t)(row + 8) * E + col] =
                    __floats2half2_rn(acc[mt][nt][2] + b0, acc[mt][nt][3] + b1);
            } else {
                float* C = (float*)Cv;
                *(float2*)&C[(size_t)row * E + col] =
                    make_float2(acc[mt][nt][0] + b0, acc[mt][nt][1] + b1);
                *(float2*)&C[(size_t)(row + 8) * E + col] =
                    make_float2(acc[mt][nt][2] + b0, acc[mt][nt][3] + b1);
            }
        }
    }
#undef LOAD_STAGE
}

// ---------------------------------------------------------------------------
// Normalize mapper matrices -> zero-padded fp16
// ---------------------------------------------------------------------------
__global__ void norm_map_h(const float* __restrict__ qm, const float* __restrict__ xm,
                           __half* __restrict__ qmH, __half* __restrict__ xmH)
{
    int row  = blockIdx.x * (blockDim.x >> 5) + (threadIdx.x >> 5);
    int lane = threadIdx.x & 31;
    const __half hz = __float2half(0.0f);
    if (row < 256) {
        __half* dst = qmH + row * 112;
        if (row < NT) {
            const float* x = qm + row * NQ;
            float ss = 0.0f;
            for (int i = lane; i < NQ; i += 32) { float v = x[i]; ss += v * v; }
#pragma unroll
            for (int o = 16; o; o >>= 1) ss += __shfl_xor_sync(0xffffffffu, ss, o);
            float s = 1.0f / fmaxf(sqrtf(ss), 1e-12f);
            for (int i = lane; i < 112; i += 32)
                dst[i] = (i < NQ) ? __float2half(x[i] * s) : hz;
        } else {
            for (int i = lane; i < 112; i += 32) dst[i] = hz;
        }
    } else if (row < 384) {
        int r = row - 256;
        __half* dst = xmH + r * 256;
        if (r < NQ) {
            const float* x = xm + r * NT;
            float ss = 0.0f;
            for (int i = lane; i < NT; i += 32) { float v = x[i]; ss += v * v; }
#pragma unroll
            for (int o = 16; o; o >>= 1) ss += __shfl_xor_sync(0xffffffffu, ss, o);
            float s = 1.0f / fmaxf(sqrtf(ss), 1e-12f);
            for (int i = lane; i < 256; i += 32)
                dst[i] = (i < NT) ? __float2half(x[i] * s) : hz;
        } else {
            for (int i = lane; i < 256; i += 32) dst[i] = hz;
        }
    }
}

// ---------------------------------------------------------------------------
// Tensor-core fused attention, 85KB SMEM -> 2 CTAs/SM.
//   region1: hQ [64][120]h  (P0..P1)  /  sS [64][68]f (P2..softmax)
//            /  hP rows stride 136h in-place over sS (softmax..P4)
//   hK:      kn [64][264]h  (P0..P2)  /  sOut [128][66]f (P5..end)
//   hM:      qm [64][264]h  (P1..P2)  /  x [64][264]h (P4..P5)
//   v:       fetched in P4 as B-frags from global fp16 (predicated LDG)
// ---------------------------------------------------------------------------
#define HQ_S 120
#define HK_S 264
#define SS_S 68
#define HP_S 136
#define SO_S 66
#define OFF_R1 0
#define OFF_HK 8704
#define OFF_HM 25600
#define ATTN_HALVES 42496
#define ATTN_SMEM_BYTES (ATTN_HALVES * 2)   // 84992

__global__ __launch_bounds__(512, 2)
void attn_tc(const __half* __restrict__ q_t, const __half* __restrict__ k_t,
             const __half* __restrict__ v_t, const __half* __restrict__ qmH,
             const __half* __restrict__ xmH, const float* __restrict__ temp,
             __half* __restrict__ y)
{
    extern __shared__ __half sh[];
    __half* hQ = sh + OFF_R1;
    __half* hK = sh + OFF_HK;
    __half* hM = sh + OFF_HM;
    float*  sS   = (float*)(sh + OFF_R1);
    float*  sOut = (float*)(sh + OFF_HK);
    const uint32_t sbase = smem_u32(sh);

    const int bh = blockIdx.x;
    const int b  = bh / NH;
    const int h  = bh % NH;
    const __half* qp = q_t + (size_t)b * E + h * HD;
    const __half* kp = k_t + (size_t)b * E + h * HD;
    const __half* vp = v_t + (size_t)b * E + h * HD;

    const int tid  = threadIdx.x;
    const int wid  = tid >> 5;
    const int lane = tid & 31;
    const int g    = lane >> 3;
    const int jj   = lane & 7;
    const int r    = lane >> 2;
    const int qq   = lane & 3;

    // ---- zero region1 + hK (padding correctness) ----
    {
        uint32_t* z = (uint32_t*)sh;          // 25600 halves = 12800 words
        for (int i = tid; i < 12800; i += 512) z[i] = 0u;
    }
    __syncthreads();

    // ---- load q,k transposed to channel-major fp16 ----
    for (int i = tid; i < NQ * 32; i += 512) {
        int tok = i >> 5, c = i & 31;
        __half2 v2 = *(const __half2*)(qp + (size_t)tok * ROWSTR + 2 * c);
        hQ[(2 * c) * HQ_S + tok]     = __low2half(v2);
        hQ[(2 * c + 1) * HQ_S + tok] = __high2half(v2);
    }
    for (int i = tid; i < NT * 32; i += 512) {
        int tok = i >> 5, c = i & 31;
        __half2 v2 = *(const __half2*)(kp + (size_t)tok * ROWSTR + 2 * c);
        hK[(2 * c) * HK_S + tok]     = __low2half(v2);
        hK[(2 * c + 1) * HK_S + tok] = __high2half(v2);
    }
    __syncthreads();

    // ---- L2 norms over tokens (fp32 math on fp16 data) ----
    for (int rr = wid; rr < 128; rr += 16) {
        __half2* x; int nh2;
        if (rr < 64) { x = (__half2*)(hQ + rr * HQ_S); nh2 = 50; }
        else         { x = (__half2*)(hK + (rr - 64) * HK_S); nh2 = 100; }
        float ss = 0.0f;
        for (int i = lane; i < nh2; i += 32) {
            float2 f = __half22float2(x[i]);
            ss += f.x * f.x + f.y * f.y;
        }
#pragma unroll
        for (int o = 16; o; o >>= 1) ss += __shfl_xor_sync(0xffffffffu, ss, o);
        float sc = 1.0f / fmaxf(sqrtf(ss), 1e-12f);
        for (int i = lane; i < nh2; i += 32) {
            float2 f = __half22float2(x[i]);
            x[i] = __floats2half2_rn(f.x * sc, f.y * sc);
        }
    }
    __syncthreads();

    // ---- P1: qm[64,256] = qn @ qmH^T -> hM ----
    {
        const int mb = (wid & 3) * 16;
        const int nb = (wid >> 2) * 64;
        const uint32_t aBase = sbase +
            (OFF_R1 + (mb + jj + (g & 1) * 8) * HQ_S + (g >> 1) * 8) * 2;
        float acc[8][4];
#pragma unroll
        for (int i = 0; i < 8; i++)
#pragma unroll
            for (int k = 0; k < 4; k++) acc[i][k] = 0.0f;
        const int k0l = 2 * qq;
#pragma unroll
        for (int kk = 0; kk < 7; kk++) {
            uint32_t af[4];
            ldsm4(af[0], af[1], af[2], af[3], aBase + kk * 32);
#pragma unroll
            for (int nb8 = 0; nb8 < 8; nb8++) {
                const __half* bp = qmH + (nb + nb8 * 8 + r) * 112 + kk * 16 + k0l;
                uint32_t bf[2];
                bf[0] = *(const uint32_t*)bp;
                bf[1] = *(const uint32_t*)(bp + 8);
                mma_f16(acc[nb8], af, bf);
            }
        }
#pragma unroll
        for (int nb8 = 0; nb8 < 8; nb8++) {
            int col = nb + nb8 * 8 + 2 * qq;
            *(__half2*)&hM[(mb + r) * HK_S + col]     = __floats2half2_rn(acc[nb8][0], acc[nb8][1]);
            *(__half2*)&hM[(mb + r + 8) * HK_S + col] = __floats2half2_rn(acc[nb8][2], acc[nb8][3]);
        }
    }
    __syncthreads();

    // ---- P2: S[64,64] = qm @ kn^T -> sS fp32 (scaled) ----
    {
        const int mb = (wid & 3) * 16;
        const int nb = (wid >> 2) * 16;
        const uint32_t aBase = sbase +
            (OFF_HM + (mb + jj + (g & 1) * 8) * HK_S + (g >> 1) * 8) * 2;
        const uint32_t bBase = sbase +
            (OFF_HK + (nb + jj + (g & 1) * 8) * HK_S + (g >> 1) * 8) * 2;
        float acc[2][4];
#pragma unroll
        for (int i = 0; i < 2; i++)
#pragma unroll
            for (int k = 0; k < 4; k++) acc[i][k] = 0.0f;
#pragma unroll
        for (int kk = 0; kk < 16; kk++) {
            uint32_t af[4], b0, b1, b2, b3;
            ldsm4(af[0], af[1], af[2], af[3], aBase + kk * 32);
            ldsm4(b0, b1, b2, b3, bBase + kk * 32);
            uint32_t bfA[2] = {b0, b2}, bfB[2] = {b1, b3};
            mma_f16(acc[0], af, bfA);
            mma_f16(acc[1], af, bfB);
        }
        __syncthreads();   // hQ region (region1) dead; sS overlays it
        const float tval = temp[h];
#pragma unroll
        for (int t = 0; t < 2; t++) {
            int col = nb + t * 8 + 2 * qq;
            sS[(mb + r) * SS_S + col]         = acc[t][0] * tval;
            sS[(mb + r) * SS_S + col + 1]     = acc[t][1] * tval;
            sS[(mb + r + 8) * SS_S + col]     = acc[t][2] * tval;
            sS[(mb + r + 8) * SS_S + col + 1] = acc[t][3] * tval;
        }
    }
    __syncthreads();

    // ---- softmax rows of sS -> hP fp16 in place (write trails read) ----
    if (tid < 64) {
        float* rw = sS + tid * SS_S;
        __half* pp = (__half*)rw;
        float mx = rw[0];
#pragma unroll 8
        for (int e = 1; e < 64; e++) mx = fmaxf(mx, rw[e]);
        float s = 0.0f;
        float ex[64];
#pragma unroll 8
        for (int e = 0; e < 64; e++) { ex[e] = __expf(rw[e] - mx); s += ex[e]; }
        float inv = 1.0f / s;
#pragma unroll 8
        for (int e = 0; e < 64; e++) pp[e] = __float2half(ex[e] * inv);
    }
    __syncthreads();

    // ---- P4: x[64,256] = P @ v^T -> hM (v B-frags from global, predicated) ----
    {
        const int mb = (wid & 3) * 16;
        const int nb = (wid >> 2) * 64;
        const uint32_t aBase = sbase +
            (OFF_R1 + (mb + jj + (g & 1) * 8) * HP_S + (g >> 1) * 8) * 2;
        float acc[8][4];
#pragma unroll
        for (int i = 0; i < 8; i++)
#pragma unroll
            for (int k = 0; k < 4; k++) acc[i][k] = 0.0f;
        const int k0l = 2 * qq;
#pragma unroll
        for (int kk = 0; kk < 4; kk++) {
            uint32_t af[4];
            ldsm4(af[0], af[1], af[2], af[3], aBase + kk * 32);
#pragma unroll
            for (int nb8 = 0; nb8 < 8; nb8++) {
                const int row = nb + nb8 * 8 + r;
                uint32_t bf[2] = {0u, 0u};
                if (row < NT) {
                    const __half* bp = vp + (size_t)row * ROWSTR + kk * 16 + k0l;
                    bf[0] = *(const uint32_t*)bp;
                    bf[1] = *(const uint32_t*)(bp + 8);
                }
                mma_f16(acc[nb8], af, bf);
            }
        }
#pragma unroll
        for (int nb8 = 0; nb8 < 8; nb8++) {
            int col = nb + nb8 * 8 + 2 * qq;
            *(__half2*)&hM[(mb + r) * HK_S + col]     = __floats2half2_rn(acc[nb8][0], acc[nb8][1]);
            *(__half2*)&hM[(mb + r + 8) * HK_S + col] = __floats2half2_rn(acc[nb8][2], acc[nb8][3]);
        }
    }
    __syncthreads();

    // ---- P5: out[64,128] = x @ xmH^T -> sOut fp32 [q][d] (overlays hK) ----
    {
        const int mb = (wid & 3) * 16;
        const int nb = (wid >> 2) * 32;
        const uint32_t aBase = sbase +
            (OFF_HM + (mb + jj + (g & 1) * 8) * HK_S + (g >> 1) * 8) * 2;
        float acc[4][4];
#pragma unroll
        for (int i = 0; i < 4; i++)
#pragma unroll
            for (int k = 0; k < 4; k++) acc[i][k] = 0.0f;
        const int k0l = 2 * qq;
#pragma unroll
        for (int kk = 0; kk < 16; kk++) {
            uint32_t af[4];
            ldsm4(af[0], af[1], af[2], af[3], aBase + kk * 32);
#pragma unroll
            for (int nb8 = 0; nb8 < 4; nb8++) {
                const __half* bp = xmH + (nb + nb8 * 8 + r) * 256 + kk * 16 + k0l;
                uint32_t bf[2];
                bf[0] = *(const uint32_t*)bp;
                bf[1] = *(const uint32_t*)(bp + 8);
                mma_f16(acc[nb8], af, bf);
            }
        }
#pragma unroll
        for (int nb8 = 0; nb8 < 4; nb8++) {
            int q0 = nb + nb8 * 8 + 2 * qq;
            int d0 = mb + r;
            sOut[q0 * SO_S + d0]           = acc[nb8][0];
            sOut[(q0 + 1) * SO_S + d0]     = acc[nb8][1];
            sOut[q0 * SO_S + d0 + 8]       = acc[nb8][2];
            sOut[(q0 + 1) * SO_S + d0 + 8] = acc[nb8][3];
        }
    }
    __syncthreads();

    // ---- epilogue: coalesced fp16 store of q<100 rows ----
    for (int i = tid; i < NQ * 32; i += 512) {
        int q = i >> 5, c = i & 31;
        float a0 = sOut[q * SO_S + 2 * c];
        float a1 = sOut[q * SO_S + 2 * c + 1];
        *(__half2*)&y[((size_t)q * BSZ + b) * E + h * HD + 2 * c] =
            __floats2half2_rn(a0, a1);
    }
}

// ---------------------------------------------------------------------------
// Launch
// ---------------------------------------------------------------------------
extern "C" void kernel_launch(void* const* d_in, const int* in_sizes, int n_in,
                              void* d_out, int out_size)
{
    const float* query = (const float*)d_in[0];
    const float* key   = (const float*)d_in[1];
    const float* value = (const float*)d_in[2];
    const float* ipw   = (const float*)d_in[3];
    const float* ipb   = (const float*)d_in[4];
    const float* opw   = (const float*)d_in[5];
    const float* opb   = (const float*)d_in[6];
    const float* temp  = (const float*)d_in[7];
    const float* qmap  = (const float*)d_in[8];
    const float* xmap  = (const float*)d_in[9];
    float* out = (float*)d_out;

    __half *qh, *kh, *vh, *wh, *owh, *yh, *qmH, *xmH, *qph, *kph, *vph;
    cudaGetSymbolAddress((void**)&qh,  g_qh);
    cudaGetSymbolAddress((void**)&kh,  g_kh);
    cudaGetSymbolAddress((void**)&vh,  g_vh);
    cudaGetSymbolAddress((void**)&wh,  g_wh);
    cudaGetSymbolAddress((void**)&owh, g_owh);
    cudaGetSymbolAddress((void**)&yh,  g_yh);
    cudaGetSymbolAddress((void**)&qmH, g_qmH);
    cudaGetSymbolAddress((void**)&xmH, g_xmH);
    cudaGetSymbolAddress((void**)&qph, g_qph);
    cudaGetSymbolAddress((void**)&kph, g_kph);
    cudaGetSymbolAddress((void**)&vph, g_vph);

    cudaFuncSetAttribute(gemm_h<true>,  cudaFuncAttributeMaxDynamicSharedMemorySize, GEMM_SMEM);
    cudaFuncSetAttribute(gemm_h<false>, cudaFuncAttributeMaxDynamicSharedMemorySize, GEMM_SMEM);
    cudaFuncSetAttribute(attn_tc, cudaFuncAttributeMaxDynamicSharedMemorySize,
                         ATTN_SMEM_BYTES);

    auto conv = [](const float* src, __half* dst, int n) {
        int n4 = n / 4;
        f2h<<<(n4 + 255) / 256, 256>>>((const float4*)src, (__half2*)dst, n4);
    };

    dim3 gq(6, (NQ * BSZ) / 128);
    dim3 gk(6, (NT * BSZ) / 128);

    norm_map_h<<<48, 256>>>(qmap, xmap, qmH, xmH);
    conv(query, qh, NQ * BSZ * E);
    conv(ipw,   wh, 3 * E * E);
    gemm_h<true><<<gq, 256, GEMM_SMEM>>>(qh, wh, ipb, qph);
    conv(key,   kh, NT * BSZ * E);
    conv(value, vh, NT * BSZ * E);
    conv(opw,   owh, E * E);
    gemm_h<true><<<gk, 256, GEMM_SMEM>>>(kh, wh + E * E,     ipb + E,     kph);
    gemm_h<true><<<gk, 256, GEMM_SMEM>>>(vh, wh + 2 * E * E, ipb + 2 * E, vph);
    attn_tc<<<BH, 512, ATTN_SMEM_BYTES>>>(qph, kph, vph, qmH, xmH, temp, yh);
    gemm_h<false><<<gq, 256, GEMM_SMEM>>>(yh, owh, opb, out);
}

// round 14
// speedup vs baseline: 2.7805x; 1.0066x over previous
#include <cuda_runtime.h>
#include <cuda_fp16.h>
#include <math.h>
#include <cstdint>

// Problem constants
#define NQ   100
#define NT   197
#define BSZ  128
#define E    768
#define NH   12
#define HD   64
#define BH   (BSZ*NH)
#define ROWSTR ((size_t)BSZ * E)

// ---------------------------------------------------------------------------
// Device scratch
// ---------------------------------------------------------------------------
__device__ __half g_qh[NQ * BSZ * E];      // fp16 inputs to projections
__device__ __half g_kh[NT * BSZ * E];
__device__ __half g_vh[NT * BSZ * E];
__device__ __half g_wh[3 * E * E];
__device__ __half g_owh[E * E];
__device__ __half g_qph[BH * NQ * HD];     // fp16 projections, [bh][tok][d]
__device__ __half g_kph[BH * NT * HD];
__device__ __half g_vph[BH * NT * HD];
__device__ __half g_yh[NQ * BSZ * E];      // fp16 attention output (row-major)
__device__ __half g_qmH[256 * 112];        // normalized q_mapper fp16 [t][q], zero-pad
__device__ __half g_xmH[128 * 256];        // normalized x_mapper fp16 [q][t], zero-pad

// ---------------------------------------------------------------------------
// Common PTX helpers
// ---------------------------------------------------------------------------
__device__ __forceinline__ uint32_t smem_u32(const void* p) {
    uint32_t a;
    asm("{ .reg .u64 t; cvta.to.shared.u64 t, %1; cvt.u32.u64 %0, t; }"
        : "=r"(a) : "l"(p));
    return a;
}
__device__ __forceinline__ void cpa16(uint32_t dst, const void* src) {
    asm volatile("cp.async.cg.shared.global [%0], [%1], 16;" :: "r"(dst), "l"(src));
}
__device__ __forceinline__ void ldsm4(uint32_t& r0, uint32_t& r1, uint32_t& r2,
                                      uint32_t& r3, uint32_t addr) {
    asm volatile("ldmatrix.sync.aligned.m8n8.x4.shared.b16 {%0,%1,%2,%3}, [%4];"
                 : "=r"(r0), "=r"(r1), "=r"(r2), "=r"(r3) : "r"(addr));
}
__device__ __forceinline__ void mma_f16(float* c, const uint32_t* a, const uint32_t* b) {
    asm volatile(
        "mma.sync.aligned.m16n8k16.row.col.f32.f16.f16.f32 "
        "{%0,%1,%2,%3}, {%4,%5,%6,%7}, {%8,%9}, {%0,%1,%2,%3};"
        : "+f"(c[0]), "+f"(c[1]), "+f"(c[2]), "+f"(c[3])
        : "r"(a[0]), "r"(a[1]), "r"(a[2]), "r"(a[3]), "r"(b[0]), "r"(b[1]));
}

// ---------------------------------------------------------------------------
// fp32 -> fp16 conversion
// ---------------------------------------------------------------------------
__global__ void f2h(const float4* __restrict__ in, __half2* __restrict__ out, int n4)
{
    int i = blockIdx.x * blockDim.x + threadIdx.x;
    if (i < n4) {
        float4 v = in[i];
        out[2 * i]     = __floats2half2_rn(v.x, v.y);
        out[2 * i + 1] = __floats2half2_rn(v.z, v.w);
    }
}

// ---------------------------------------------------------------------------
// fp16 mma.sync GEMM.
//   OUTH=true : fp16 output scattered to [(b*NH+h)*NTOK + tok][d]
//               (tok == blockIdx.y because each 128-row M-tile is one token)
//   OUTH=false: fp32 output row-major [M][768]
// ---------------------------------------------------------------------------
#define PADH      40
#define MAT_H     (128 * PADH)
#define STG_B     (2 * MAT_H * 2)
#define GEMM_SMEM (4 * STG_B)

template<bool OUTH>
__global__ __launch_bounds__(256, 2)
void gemm_h(const __half* __restrict__ A, const __half* __restrict__ W,
            const float* __restrict__ bias, void* __restrict__ Cv, int NTOK)
{
    extern __shared__ __half smh[];
    const uint32_t sb = smem_u32(smh);
    const int tid  = threadIdx.x;
    const int lane = tid & 31;
    const int wid  = tid >> 5;
    const int m0 = blockIdx.y * 128, n0 = blockIdx.x * 128;
    const int wm = (wid >> 2) * 64;
    const int wn = (wid & 3) * 32;

    const int prow = tid >> 1;
    const int pseg = (tid & 1) * 16;
    const __half* gA = A + (size_t)(m0 + prow) * E + pseg;
    const __half* gB = W + (size_t)(n0 + prow) * E + pseg;
    const uint32_t sAa = sb + (prow * PADH + pseg) * 2;
    const uint32_t sBa = sAa + MAT_H * 2;

#define LOAD_STAGE(st, kc) do { \
    const uint32_t so = (uint32_t)(st) * STG_B; \
    const __half* ga = gA + (kc) * 32; \
    const __half* gb = gB + (kc) * 32; \
    cpa16(sAa + so,      ga);     cpa16(sAa + so + 16, ga + 8); \
    cpa16(sBa + so,      gb);     cpa16(sBa + so + 16, gb + 8); \
    asm volatile("cp.async.commit_group;"); \
} while (0)

    LOAD_STAGE(0, 0);
    LOAD_STAGE(1, 1);
    LOAD_STAGE(2, 2);

    float acc[4][4][4];
#pragma unroll
    for (int i = 0; i < 4; i++)
#pragma unroll
        for (int j = 0; j < 4; j++)
#pragma unroll
            for (int k = 0; k < 4; k++) acc[i][j][k] = 0.0f;

    const int g = lane >> 3, j = lane & 7;
    const uint32_t aoff = ((wm + j + (g & 1) * 8) * PADH + (g >> 1) * 8) * 2;
    const uint32_t boff = ((wn + j + (g & 1) * 8) * PADH + (g >> 1) * 8) * 2 + MAT_H * 2;

    for (int kc = 0; kc < 24; kc++) {
        asm volatile("cp.async.wait_group 2;");
        __syncthreads();
        const uint32_t base = sb + (uint32_t)(kc & 3) * STG_B;

#pragma unroll
        for (int s = 0; s < 2; s++) {
            const uint32_t k0b = s * 32;
            uint32_t bf[4][2];
            ldsm4(bf[0][0], bf[1][0], bf[0][1], bf[1][1], base + boff + k0b);
            ldsm4(bf[2][0], bf[3][0], bf[2][1], bf[3][1],
                  base + boff + 16 * PADH * 2 + k0b);
#pragma unroll
            for (int mt = 0; mt < 4; mt++) {
                uint32_t af[4];
                ldsm4(af[0], af[1], af[2], af[3],
                      base + aoff + mt * 16 * PADH * 2 + k0b);
#pragma unroll
                for (int nt = 0; nt < 4; nt++)
                    mma_f16(acc[mt][nt], af, bf[nt]);
            }
        }
        if (kc + 3 < 24) {
            LOAD_STAGE((kc + 3) & 3, kc + 3);
        } else {
            asm volatile("cp.async.commit_group;");
        }
    }

    const int r = lane >> 2, q = lane & 3;
#pragma unroll
    for (int mt = 0; mt < 4; mt++) {
        const int row = m0 + wm + mt * 16 + r;
#pragma unroll
        for (int nt = 0; nt < 4; nt++) {
            const int col = n0 + wn + nt * 8 + 2 * q;
            const float b0 = bias[col], b1 = bias[col + 1];
            if (OUTH) {
                // row = tok*128 + b with tok == blockIdx.y; col = h*64 + d
                __half* C = (__half*)Cv;
                const int tok = blockIdx.y;
                const int bb  = row & 127;
                const int h   = col >> 6, d = col & 63;
                const size_t base0 = ((size_t)(bb * NH + h) * NTOK + tok) * HD + d;
                const size_t base1 = ((size_t)(((row + 8) & 127) * NH + h) * NTOK + tok) * HD + d;
                *(__half2*)&C[base0] =
                    __floats2half2_rn(acc[mt][nt][0] + b0, acc[mt][nt][1] + b1);
                *(__half2*)&C[base1] =
                    __floats2half2_rn(acc[mt][nt][2] + b0, acc[mt][nt][3] + b1);
            } else {
                float* C = (float*)Cv;
                *(float2*)&C[(size_t)row * E + col] =
                    make_float2(acc[mt][nt][0] + b0, acc[mt][nt][1] + b1);
                *(float2*)&C[(size_t)(row + 8) * E + col] =
                    make_float2(acc[mt][nt][2] + b0, acc[mt][nt][3] + b1);
            }
        }
    }
#undef LOAD_STAGE
}

// ---------------------------------------------------------------------------
// Normalize mapper matrices -> zero-padded fp16
// ---------------------------------------------------------------------------
__global__ void norm_map_h(const float* __restrict__ qm, const float* __restrict__ xm,
                           __half* __restrict__ qmH, __half* __restrict__ xmH)
{
    int row  = blockIdx.x * (blockDim.x >> 5) + (threadIdx.x >> 5);
    int lane = threadIdx.x & 31;
    const __half hz = __float2half(0.0f);
    if (row < 256) {
        __half* dst = qmH + row * 112;
        if (row < NT) {
            const float* x = qm + row * NQ;
            float ss = 0.0f;
            for (int i = lane; i < NQ; i += 32) { float v = x[i]; ss += v * v; }
#pragma unroll
            for (int o = 16; o; o >>= 1) ss += __shfl_xor_sync(0xffffffffu, ss, o);
            float s = 1.0f / fmaxf(sqrtf(ss), 1e-12f);
            for (int i = lane; i < 112; i += 32)
                dst[i] = (i < NQ) ? __float2half(x[i] * s) : hz;
        } else {
            for (int i = lane; i < 112; i += 32) dst[i] = hz;
        }
    } else if (row < 384) {
        int r = row - 256;
        __half* dst = xmH + r * 256;
        if (r < NQ) {
            const float* x = xm + r * NT;
            float ss = 0.0f;
            for (int i = lane; i < NT; i += 32) { float v = x[i]; ss += v * v; }
#pragma unroll
            for (int o = 16; o; o >>= 1) ss += __shfl_xor_sync(0xffffffffu, ss, o);
            float s = 1.0f / fmaxf(sqrtf(ss), 1e-12f);
            for (int i = lane; i < 256; i += 32)
                dst[i] = (i < NT) ? __float2half(x[i] * s) : hz;
        } else {
            for (int i = lane; i < 256; i += 32) dst[i] = hz;
        }
    }
}

// ---------------------------------------------------------------------------
// Tensor-core fused attention, 85KB SMEM -> 2 CTAs/SM.
// q/k/v now contiguous per (b,h): q_t[bh][tok][d] etc. -> coalesced loads,
// v fetched in P4 as B-frags from a hot 25KB L2 window.
// ---------------------------------------------------------------------------
#define HQ_S 120
#define HK_S 264
#define SS_S 68
#define HP_S 136
#define SO_S 66
#define OFF_R1 0
#define OFF_HK 8704
#define OFF_HM 25600
#define ATTN_HALVES 42496
#define ATTN_SMEM_BYTES (ATTN_HALVES * 2)   // 84992

__global__ __launch_bounds__(512, 2)
void attn_tc(const __half* __restrict__ q_t, const __half* __restrict__ k_t,
             const __half* __restrict__ v_t, const __half* __restrict__ qmH,
             const __half* __restrict__ xmH, const float* __restrict__ temp,
             __half* __restrict__ y)
{
    extern __shared__ __half sh[];
    __half* hQ = sh + OFF_R1;
    __half* hK = sh + OFF_HK;
    __half* hM = sh + OFF_HM;
    float*  sS   = (float*)(sh + OFF_R1);
    float*  sOut = (float*)(sh + OFF_HK);
    const uint32_t sbase = smem_u32(sh);

    const int bh = blockIdx.x;
    const int b  = bh / NH;
    const int h  = bh % NH;
    const __half* qp = q_t + (size_t)bh * (NQ * HD);
    const __half* kp = k_t + (size_t)bh * (NT * HD);
    const __half* vp = v_t + (size_t)bh * (NT * HD);

    const int tid  = threadIdx.x;
    const int wid  = tid >> 5;
    const int lane = tid & 31;
    const int g    = lane >> 3;
    const int jj   = lane & 7;
    const int r    = lane >> 2;
    const int qq   = lane & 3;

    // ---- zero region1 + hK (padding correctness) ----
    {
        uint32_t* z = (uint32_t*)sh;
        for (int i = tid; i < 12800; i += 512) z[i] = 0u;
    }
    __syncthreads();

    // ---- load q,k transposed to channel-major fp16 (coalesced 128B/tok) ----
    for (int i = tid; i < NQ * 32; i += 512) {
        int tok = i >> 5, c = i & 31;
        __half2 v2 = *(const __half2*)(qp + tok * HD + 2 * c);
        hQ[(2 * c) * HQ_S + tok]     = __low2half(v2);
        hQ[(2 * c + 1) * HQ_S + tok] = __high2half(v2);
    }
    for (int i = tid; i < NT * 32; i += 512) {
        int tok = i >> 5, c = i & 31;
        __half2 v2 = *(const __half2*)(kp + tok * HD + 2 * c);
        hK[(2 * c) * HK_S + tok]     = __low2half(v2);
        hK[(2 * c + 1) * HK_S + tok] = __high2half(v2);
    }
    __syncthreads();

    // ---- L2 norms over tokens (fp32 math on fp16 data) ----
    for (int rr = wid; rr < 128; rr += 16) {
        __half2* x; int nh2;
        if (rr < 64) { x = (__half2*)(hQ + rr * HQ_S); nh2 = 50; }
        else         { x = (__half2*)(hK + (rr - 64) * HK_S); nh2 = 100; }
        float ss = 0.0f;
        for (int i = lane; i < nh2; i += 32) {
            float2 f = __half22float2(x[i]);
            ss += f.x * f.x + f.y * f.y;
        }
#pragma unroll
        for (int o = 16; o; o >>= 1) ss += __shfl_xor_sync(0xffffffffu, ss, o);
        float sc = 1.0f / fmaxf(sqrtf(ss), 1e-12f);
        for (int i = lane; i < nh2; i += 32) {
            float2 f = __half22float2(x[i]);
            x[i] = __floats2half2_rn(f.x * sc, f.y * sc);
        }
    }
    __syncthreads();

    // ---- P1: qm[64,256] = qn @ qmH^T -> hM ----
    {
        const int mb = (wid & 3) * 16;
        const int nb = (wid >> 2) * 64;
        const uint32_t aBase = sbase +
            (OFF_R1 + (mb + jj + (g & 1) * 8) * HQ_S + (g >> 1) * 8) * 2;
        float acc[8][4];
#pragma unroll
        for (int i = 0; i < 8; i++)
#pragma unroll
            for (int k = 0; k < 4; k++) acc[i][k] = 0.0f;
        const int k0l = 2 * qq;
#pragma unroll
        for (int kk = 0; kk < 7; kk++) {
            uint32_t af[4];
            ldsm4(af[0], af[1], af[2], af[3], aBase + kk * 32);
#pragma unroll
            for (int nb8 = 0; nb8 < 8; nb8++) {
                const __half* bp = qmH + (nb + nb8 * 8 + r) * 112 + kk * 16 + k0l;
                uint32_t bf[2];
                bf[0] = *(const uint32_t*)bp;
                bf[1] = *(const uint32_t*)(bp + 8);
                mma_f16(acc[nb8], af, bf);
            }
        }
#pragma unroll
        for (int nb8 = 0; nb8 < 8; nb8++) {
            int col = nb + nb8 * 8 + 2 * qq;
            *(__half2*)&hM[(mb + r) * HK_S + col]     = __floats2half2_rn(acc[nb8][0], acc[nb8][1]);
            *(__half2*)&hM[(mb + r + 8) * HK_S + col] = __floats2half2_rn(acc[nb8][2], acc[nb8][3]);
        }
    }
    __syncthreads();

    // ---- P2: S[64,64] = qm @ kn^T -> sS fp32 (scaled) ----
    {
        const int mb = (wid & 3) * 16;
        const int nb = (wid >> 2) * 16;
        const uint32_t aBase = sbase +
            (OFF_HM + (mb + jj + (g & 1) * 8) * HK_S + (g >> 1) * 8) * 2;
        const uint32_t bBase = sbase +
            (OFF_HK + (nb + jj + (g & 1) * 8) * HK_S + (g >> 1) * 8) * 2;
        float acc[2][4];
#pragma unroll
        for (int i = 0; i < 2; i++)
#pragma unroll
            for (int k = 0; k < 4; k++) acc[i][k] = 0.0f;
#pragma unroll
        for (int kk = 0; kk < 16; kk++) {
            uint32_t af[4], b0, b1, b2, b3;
            ldsm4(af[0], af[1], af[2], af[3], aBase + kk * 32);
            ldsm4(b0, b1, b2, b3, bBase + kk * 32);
            uint32_t bfA[2] = {b0, b2}, bfB[2] = {b1, b3};
            mma_f16(acc[0], af, bfA);
            mma_f16(acc[1], af, bfB);
        }
        __syncthreads();   // hQ region dead; sS overlays it
        const float tval = temp[h];
#pragma unroll
        for (int t = 0; t < 2; t++) {
            int col = nb + t * 8 + 2 * qq;
            sS[(mb + r) * SS_S + col]         = acc[t][0] * tval;
            sS[(mb + r) * SS_S + col + 1]     = acc[t][1] * tval;
            sS[(mb + r + 8) * SS_S + col]     = acc[t][2] * tval;
            sS[(mb + r + 8) * SS_S + col + 1] = acc[t][3] * tval;
        }
    }
    __syncthreads();

    // ---- softmax rows of sS -> hP fp16 in place ----
    if (tid < 64) {
        float* rw = sS + tid * SS_S;
        __half* pp = (__half*)rw;
        float mx = rw[0];
#pragma unroll 8
        for (int e = 1; e < 64; e++) mx = fmaxf(mx, rw[e]);
        float s = 0.0f;
        float ex[64];
#pragma unroll 8
        for (int e = 0; e < 64; e++) { ex[e] = __expf(rw[e] - mx); s += ex[e]; }
        float inv = 1.0f / s;
#pragma unroll 8
        for (int e = 0; e < 64; e++) pp[e] = __float2half(ex[e] * inv);
    }
    __syncthreads();

    // ---- P4: x[64,256] = P @ v^T -> hM (v B-frags from contiguous global) ----
    {
        const int mb = (wid & 3) * 16;
        const int nb = (wid >> 2) * 64;
        const uint32_t aBase = sbase +
            (OFF_R1 + (mb + jj + (g & 1) * 8) * HP_S + (g >> 1) * 8) * 2;
        float acc[8][4];
#pragma unroll
        for (int i = 0; i < 8; i++)
#pragma unroll
            for (int k = 0; k < 4; k++) acc[i][k] = 0.0f;
        const int k0l = 2 * qq;
#pragma unroll
        for (int kk = 0; kk < 4; kk++) {
            uint32_t af[4];
            ldsm4(af[0], af[1], af[2], af[3], aBase + kk * 32);
#pragma unroll
            for (int nb8 = 0; nb8 < 8; nb8++) {
                const int row = nb + nb8 * 8 + r;
                uint32_t bf[2] = {0u, 0u};
                if (row < NT) {
                    const __half* bp = vp + row * HD + kk * 16 + k0l;
                    bf[0] = *(const uint32_t*)bp;
                    bf[1] = *(const uint32_t*)(bp + 8);
                }
                mma_f16(acc[nb8], af, bf);
            }
        }
#pragma unroll
        for (int nb8 = 0; nb8 < 8; nb8++) {
            int col = nb + nb8 * 8 + 2 * qq;
            *(__half2*)&hM[(mb + r) * HK_S + col]     = __floats2half2_rn(acc[nb8][0], acc[nb8][1]);
            *(__half2*)&hM[(mb + r + 8) * HK_S + col] = __floats2half2_rn(acc[nb8][2], acc[nb8][3]);
        }
    }
    __syncthreads();

    // ---- P5: out[64,128] = x @ xmH^T -> sOut fp32 [q][d] (overlays hK) ----
    {
        const int mb = (wid & 3) * 16;
        const int nb = (wid >> 2) * 32;
        const uint32_t aBase = sbase +
            (OFF_HM + (mb + jj + (g & 1) * 8) * HK_S + (g >> 1) * 8) * 2;
        float acc[4][4];
#pragma unroll
        for (int i = 0; i < 4; i++)
#pragma unroll
            for (int k = 0; k < 4; k++) acc[i][k] = 0.0f;
        const int k0l = 2 * qq;
#pragma unroll
        for (int kk = 0; kk < 16; kk++) {
            uint32_t af[4];
            ldsm4(af[0], af[1], af[2], af[3], aBase + kk * 32);
#pragma unroll
            for (int nb8 = 0; nb8 < 4; nb8++) {
                const __half* bp = xmH + (nb + nb8 * 8 + r) * 256 + kk * 16 + k0l;
                uint32_t bf[2];
                bf[0] = *(const uint32_t*)bp;
                bf[1] = *(const uint32_t*)(bp + 8);
                mma_f16(acc[nb8], af, bf);
            }
        }
#pragma unroll
        for (int nb8 = 0; nb8 < 4; nb8++) {
            int q0 = nb + nb8 * 8 + 2 * qq;
            int d0 = mb + r;
            sOut[q0 * SO_S + d0]           = acc[nb8][0];
            sOut[(q0 + 1) * SO_S + d0]     = acc[nb8][1];
            sOut[q0 * SO_S + d0 + 8]       = acc[nb8][2];
            sOut[(q0 + 1) * SO_S + d0 + 8] = acc[nb8][3];
        }
    }
    __syncthreads();

    // ---- epilogue: coalesced fp16 store of q<100 rows (row-major y) ----
    for (int i = tid; i < NQ * 32; i += 512) {
        int q = i >> 5, c = i & 31;
        float a0 = sOut[q * SO_S + 2 * c];
        float a1 = sOut[q * SO_S + 2 * c + 1];
        *(__half2*)&y[((size_t)q * BSZ + b) * E + h * HD + 2 * c] =
            __floats2half2_rn(a0, a1);
    }
}

// ---------------------------------------------------------------------------
// Launch (gemm_h in slot 4 for profiling)
// ---------------------------------------------------------------------------
extern "C" void kernel_launch(void* const* d_in, const int* in_sizes, int n_in,
                              void* d_out, int out_size)
{
    const float* query = (const float*)d_in[0];
    const float* key   = (const float*)d_in[1];
    const float* value = (const float*)d_in[2];
    const float* ipw   = (const float*)d_in[3];
    const float* ipb   = (const float*)d_in[4];
    const float* opw   = (const float*)d_in[5];
    const float* opb   = (const float*)d_in[6];
    const float* temp  = (const float*)d_in[7];
    const float* qmap  = (const float*)d_in[8];
    const float* xmap  = (const float*)d_in[9];
    float* out = (float*)d_out;

    __half *qh, *kh, *vh, *wh, *owh, *yh, *qmH, *xmH, *qph, *kph, *vph;
    cudaGetSymbolAddress((void**)&qh,  g_qh);
    cudaGetSymbolAddress((void**)&kh,  g_kh);
    cudaGetSymbolAddress((void**)&vh,  g_vh);
    cudaGetSymbolAddress((void**)&wh,  g_wh);
    cudaGetSymbolAddress((void**)&owh, g_owh);
    cudaGetSymbolAddress((void**)&yh,  g_yh);
    cudaGetSymbolAddress((void**)&qmH, g_qmH);
    cudaGetSymbolAddress((void**)&xmH, g_xmH);
    cudaGetSymbolAddress((void**)&qph, g_qph);
    cudaGetSymbolAddress((void**)&kph, g_kph);
    cudaGetSymbolAddress((void**)&vph, g_vph);

    cudaFuncSetAttribute(gemm_h<true>,  cudaFuncAttributeMaxDynamicSharedMemorySize, GEMM_SMEM);
    cudaFuncSetAttribute(gemm_h<false>, cudaFuncAttributeMaxDynamicSharedMemorySize, GEMM_SMEM);
    cudaFuncSetAttribute(attn_tc, cudaFuncAttributeMaxDynamicSharedMemorySize,
                         ATTN_SMEM_BYTES);

    auto conv = [](const float* src, __half* dst, int n) {
        int n4 = n / 4;
        f2h<<<(n4 + 255) / 256, 256>>>((const float4*)src, (__half2*)dst, n4);
    };

    dim3 gq(6, (NQ * BSZ) / 128);
    dim3 gk(6, (NT * BSZ) / 128);

    norm_map_h<<<48, 256>>>(qmap, xmap, qmH, xmH);
    conv(query, qh, NQ * BSZ * E);
    conv(ipw,   wh, 3 * E * E);
    gemm_h<true><<<gq, 256, GEMM_SMEM>>>(qh, wh, ipb, qph, NQ);
    conv(key,   kh, NT * BSZ * E);
    conv(value, vh, NT * BSZ * E);
    conv(opw,   owh, E * E);
    gemm_h<true><<<gk, 256, GEMM_SMEM>>>(kh, wh + E * E,     ipb + E,     kph, NT);
    gemm_h<true><<<gk, 256, GEMM_SMEM>>>(vh, wh + 2 * E * E, ipb + 2 * E, vph, NT);
    attn_tc<<<BH, 512, ATTN_SMEM_BYTES>>>(qph, kph, vph, qmH, xmH, temp, yh);
    gemm_h<false><<<gq, 256, GEMM_SMEM>>>(yh, owh, opb, out, 0);
}

// round 15
// speedup vs baseline: 2.9834x; 1.0730x over previous
#include <cuda_runtime.h>
#include <cuda_fp16.h>
#include <math.h>
#include <cstdint>

// Problem constants
#define NQ   100
#define NT   197
#define BSZ  128
#define E    768
#define NH   12
#define HD   64
#define BH   (BSZ*NH)

// ---------------------------------------------------------------------------
// Device scratch
// ---------------------------------------------------------------------------
__device__ __half g_qh[NQ * BSZ * E];      // fp16 inputs to projections
__device__ __half g_kh[NT * BSZ * E];
__device__ __half g_vh[NT * BSZ * E];
__device__ __half g_wh[3 * E * E];
__device__ __half g_owh[E * E];
__device__ __half g_qph[BH * NQ * HD];     // fp16 projections, [bh][tok][d]
__device__ __half g_kph[BH * NT * HD];
__device__ __half g_vph[BH * NT * HD];
__device__ __half g_yh[NQ * BSZ * E];      // fp16 attention output (row-major)
__device__ __half g_qmH[256 * 112];        // normalized q_mapper fp16 [t][q], zero-pad
__device__ __half g_xmH[128 * 256];        // normalized x_mapper fp16 [q][t], zero-pad

// ---------------------------------------------------------------------------
// Common PTX helpers
// ---------------------------------------------------------------------------
__device__ __forceinline__ uint32_t smem_u32(const void* p) {
    uint32_t a;
    asm("{ .reg .u64 t; cvta.to.shared.u64 t, %1; cvt.u32.u64 %0, t; }"
        : "=r"(a) : "l"(p));
    return a;
}
__device__ __forceinline__ void cpa16(uint32_t dst, const void* src) {
    asm volatile("cp.async.cg.shared.global [%0], [%1], 16;" :: "r"(dst), "l"(src));
}
__device__ __forceinline__ void ldsm4(uint32_t& r0, uint32_t& r1, uint32_t& r2,
                                      uint32_t& r3, uint32_t addr) {
    asm volatile("ldmatrix.sync.aligned.m8n8.x4.shared.b16 {%0,%1,%2,%3}, [%4];"
                 : "=r"(r0), "=r"(r1), "=r"(r2), "=r"(r3) : "r"(addr));
}
__device__ __forceinline__ void ldsm4t(uint32_t& r0, uint32_t& r1, uint32_t& r2,
                                       uint32_t& r3, uint32_t addr) {
    asm volatile("ldmatrix.sync.aligned.m8n8.x4.trans.shared.b16 {%0,%1,%2,%3}, [%4];"
                 : "=r"(r0), "=r"(r1), "=r"(r2), "=r"(r3) : "r"(addr));
}
__device__ __forceinline__ void mma_f16(float* c, const uint32_t* a, const uint32_t* b) {
    asm volatile(
        "mma.sync.aligned.m16n8k16.row.col.f32.f16.f16.f32 "
        "{%0,%1,%2,%3}, {%4,%5,%6,%7}, {%8,%9}, {%0,%1,%2,%3};"
        : "+f"(c[0]), "+f"(c[1]), "+f"(c[2]), "+f"(c[3])
        : "r"(a[0]), "r"(a[1]), "r"(a[2]), "r"(a[3]), "r"(b[0]), "r"(b[1]));
}

// ---------------------------------------------------------------------------
// One fused fp32 -> fp16 conversion for all five tensors
// ---------------------------------------------------------------------------
#define NQ4 (NQ * BSZ * E / 4)
#define NT4 (NT * BSZ * E / 4)
#define W4  (3 * E * E / 4)
#define OW4 (E * E / 4)
#define TOT4 (NQ4 + 2 * NT4 + W4 + OW4)

__global__ void f2h_all(const float4* __restrict__ q, const float4* __restrict__ k,
                        const float4* __restrict__ v, const float4* __restrict__ w,
                        const float4* __restrict__ ow,
                        __half2* qh, __half2* kh, __half2* vh, __half2* wh, __half2* owh)
{
    int i = blockIdx.x * blockDim.x + threadIdx.x;
    if (i >= TOT4) return;
    const float4* src; __half2* dst; int j;
    if (i < NQ4)                        { src = q;  dst = qh;  j = i; }
    else if (i < NQ4 + NT4)             { src = k;  dst = kh;  j = i - NQ4; }
    else if (i < NQ4 + 2 * NT4)         { src = v;  dst = vh;  j = i - NQ4 - NT4; }
    else if (i < NQ4 + 2 * NT4 + W4)    { src = w;  dst = wh;  j = i - NQ4 - 2 * NT4; }
    else                                { src = ow; dst = owh; j = i - NQ4 - 2 * NT4 - W4; }
    float4 val = src[j];
    dst[2 * j]     = __floats2half2_rn(val.x, val.y);
    dst[2 * j + 1] = __floats2half2_rn(val.z, val.w);
}

// ---------------------------------------------------------------------------
// fp16 mma.sync GEMM (unchanged mainloop; scatter epilogue for OUTH=true)
// ---------------------------------------------------------------------------
#define PADH      40
#define MAT_H     (128 * PADH)
#define STG_B     (2 * MAT_H * 2)
#define GEMM_SMEM (4 * STG_B)

template<bool OUTH>
__global__ __launch_bounds__(256, 2)
void gemm_h(const __half* __restrict__ A, const __half* __restrict__ W,
            const float* __restrict__ bias, void* __restrict__ Cv, int NTOK)
{
    extern __shared__ __half smh[];
    const uint32_t sb = smem_u32(smh);
    const int tid  = threadIdx.x;
    const int lane = tid & 31;
    const int wid  = tid >> 5;
    const int m0 = blockIdx.y * 128, n0 = blockIdx.x * 128;
    const int wm = (wid >> 2) * 64;
    const int wn = (wid & 3) * 32;

    const int prow = tid >> 1;
    const int pseg = (tid & 1) * 16;
    const __half* gA = A + (size_t)(m0 + prow) * E + pseg;
    const __half* gB = W + (size_t)(n0 + prow) * E + pseg;
    const uint32_t sAa = sb + (prow * PADH + pseg) * 2;
    const uint32_t sBa = sAa + MAT_H * 2;

#define LOAD_STAGE(st, kc) do { \
    const uint32_t so = (uint32_t)(st) * STG_B; \
    const __half* ga = gA + (kc) * 32; \
    const __half* gb = gB + (kc) * 32; \
    cpa16(sAa + so,      ga);     cpa16(sAa + so + 16, ga + 8); \
    cpa16(sBa + so,      gb);     cpa16(sBa + so + 16, gb + 8); \
    asm volatile("cp.async.commit_group;"); \
} while (0)

    LOAD_STAGE(0, 0);
    LOAD_STAGE(1, 1);
    LOAD_STAGE(2, 2);

    float acc[4][4][4];
#pragma unroll
    for (int i = 0; i < 4; i++)
#pragma unroll
        for (int j = 0; j < 4; j++)
#pragma unroll
            for (int k = 0; k < 4; k++) acc[i][j][k] = 0.0f;

    const int g = lane >> 3, j = lane & 7;
    const uint32_t aoff = ((wm + j + (g & 1) * 8) * PADH + (g >> 1) * 8) * 2;
    const uint32_t boff = ((wn + j + (g & 1) * 8) * PADH + (g >> 1) * 8) * 2 + MAT_H * 2;

    for (int kc = 0; kc < 24; kc++) {
        asm volatile("cp.async.wait_group 2;");
        __syncthreads();
        const uint32_t base = sb + (uint32_t)(kc & 3) * STG_B;

#pragma unroll
        for (int s = 0; s < 2; s++) {
            const uint32_t k0b = s * 32;
            uint32_t bf[4][2];
            ldsm4(bf[0][0], bf[1][0], bf[0][1], bf[1][1], base + boff + k0b);
            ldsm4(bf[2][0], bf[3][0], bf[2][1], bf[3][1],
                  base + boff + 16 * PADH * 2 + k0b);
#pragma unroll
            for (int mt = 0; mt < 4; mt++) {
                uint32_t af[4];
                ldsm4(af[0], af[1], af[2], af[3],
                      base + aoff + mt * 16 * PADH * 2 + k0b);
#pragma unroll
                for (int nt = 0; nt < 4; nt++)
                    mma_f16(acc[mt][nt], af, bf[nt]);
            }
        }
        if (kc + 3 < 24) {
            LOAD_STAGE((kc + 3) & 3, kc + 3);
        } else {
            asm volatile("cp.async.commit_group;");
        }
    }

    const int r = lane >> 2, q = lane & 3;
#pragma unroll
    for (int mt = 0; mt < 4; mt++) {
        const int row = m0 + wm + mt * 16 + r;
#pragma unroll
        for (int nt = 0; nt < 4; nt++) {
            const int col = n0 + wn + nt * 8 + 2 * q;
            const float b0 = bias[col], b1 = bias[col + 1];
            if (OUTH) {
                __half* C = (__half*)Cv;
                const int tok = blockIdx.y;
                const int bb  = row & 127;
                const int h   = col >> 6, d = col & 63;
                const size_t base0 = ((size_t)(bb * NH + h) * NTOK + tok) * HD + d;
                const size_t base1 = ((size_t)(((row + 8) & 127) * NH + h) * NTOK + tok) * HD + d;
                *(__half2*)&C[base0] =
                    __floats2half2_rn(acc[mt][nt][0] + b0, acc[mt][nt][1] + b1);
                *(__half2*)&C[base1] =
                    __floats2half2_rn(acc[mt][nt][2] + b0, acc[mt][nt][3] + b1);
            } else {
                float* C = (float*)Cv;
                *(float2*)&C[(size_t)row * E + col] =
                    make_float2(acc[mt][nt][0] + b0, acc[mt][nt][1] + b1);
                *(float2*)&C[(size_t)(row + 8) * E + col] =
                    make_float2(acc[mt][nt][2] + b0, acc[mt][nt][3] + b1);
            }
        }
    }
#undef LOAD_STAGE
}

// ---------------------------------------------------------------------------
// Normalize mapper matrices -> zero-padded fp16
// ---------------------------------------------------------------------------
__global__ void norm_map_h(const float* __restrict__ qm, const float* __restrict__ xm,
                           __half* __restrict__ qmH, __half* __restrict__ xmH)
{
    int row  = blockIdx.x * (blockDim.x >> 5) + (threadIdx.x >> 5);
    int lane = threadIdx.x & 31;
    const __half hz = __float2half(0.0f);
    if (row < 256) {
        __half* dst = qmH + row * 112;
        if (row < NT) {
            const float* x = qm + row * NQ;
            float ss = 0.0f;
            for (int i = lane; i < NQ; i += 32) { float v = x[i]; ss += v * v; }
#pragma unroll
            for (int o = 16; o; o >>= 1) ss += __shfl_xor_sync(0xffffffffu, ss, o);
            float s = 1.0f / fmaxf(sqrtf(ss), 1e-12f);
            for (int i = lane; i < 112; i += 32)
                dst[i] = (i < NQ) ? __float2half(x[i] * s) : hz;
        } else {
            for (int i = lane; i < 112; i += 32) dst[i] = hz;
        }
    } else if (row < 384) {
        int r = row - 256;
        __half* dst = xmH + r * 256;
        if (r < NQ) {
            const float* x = xm + r * NT;
            float ss = 0.0f;
            for (int i = lane; i < NT; i += 32) { float v = x[i]; ss += v * v; }
#pragma unroll
            for (int o = 16; o; o >>= 1) ss += __shfl_xor_sync(0xffffffffu, ss, o);
            float s = 1.0f / fmaxf(sqrtf(ss), 1e-12f);
            for (int i = lane; i < 256; i += 32)
                dst[i] = (i < NT) ? __float2half(x[i] * s) : hz;
        } else {
            for (int i = lane; i < 256; i += 32) dst[i] = hz;
        }
    }
}

// ---------------------------------------------------------------------------
// Tensor-core fused attention v2.
//  - q/k loaded NATURAL [tok][64] via cp.async (coalesced, no transpose stores)
//  - trans-ldmatrix supplies qn/kn fragments
//  - L2-norm scales rs[128] folded into P2 epilogue (linearity)
//  - parallel register-only softmax (8 threads/row)
// SMEM (halves): sQ[112][72] (later sS/hP) | sK[256][72] (later sOut) |
//                hM[64][264] | rs[128]f
// ---------------------------------------------------------------------------
#define SQ_S 72
#define SK_S 72
#define HM_S 264
#define SS_S 68
#define HP_S 136
#define SO_S 66
#define OFF_SK 8704
#define OFF_HM (OFF_SK + 18432)           // 27136
#define OFF_RS (OFF_HM + 16896)           // 44032 halves
#define ATTN_SMEM_BYTES ((OFF_RS + 256) * 2)   // 88576

__global__ __launch_bounds__(512, 2)
void attn_tc(const __half* __restrict__ q_t, const __half* __restrict__ k_t,
             const __half* __restrict__ v_t, const __half* __restrict__ qmH,
             const __half* __restrict__ xmH, const float* __restrict__ temp,
             __half* __restrict__ y)
{
    extern __shared__ __half sh[];
    __half* sQ = sh;                       // [112][72] natural [tok][d]
    __half* sK = sh + OFF_SK;              // [256][72] natural [tok][e]
    __half* hM = sh + OFF_HM;              // [64][264] k-major qm / x
    float*  sS   = (float*)sh;             // [64][68]  overlays sQ after P1
    float*  sOut = (float*)(sh + OFF_SK);  // [128][66] overlays sK after P2
    float*  rs   = (float*)(sh + OFF_RS);  // [128] 1/norm scales (q:0-63, k:64-127)
    const uint32_t sbase = smem_u32(sh);

    const int bh = blockIdx.x;
    const int b  = bh / NH;
    const int h  = bh % NH;
    const __half* qp = q_t + (size_t)bh * (NQ * HD);
    const __half* kp = k_t + (size_t)bh * (NT * HD);
    const __half* vp = v_t + (size_t)bh * (NT * HD);

    const int tid  = threadIdx.x;
    const int wid  = tid >> 5;
    const int lane = tid & 31;
    const int g    = lane >> 3;
    const int jj   = lane & 7;
    const int r    = lane >> 2;
    const int qq   = lane & 3;

    // ---- zero pad tails: sQ rows 100..111, sK rows 197..255 ----
    {
        uint32_t* zq = (uint32_t*)(sQ + 100 * SQ_S);   // 432 words
        uint32_t* zk = (uint32_t*)(sK + 197 * SK_S);   // 2124 words
        for (int i = tid; i < 432 + 2124; i += 512) {
            if (i < 432) zq[i] = 0u; else zk[i - 432] = 0u;
        }
    }

    // ---- cp.async natural q/k rows (16B segments) ----
    for (int i = tid; i < (NQ + NT) * 8; i += 512) {
        if (i < NQ * 8) {
            int rr = i >> 3, s = i & 7;
            cpa16(sbase + (rr * SQ_S + s * 8) * 2, qp + rr * HD + s * 8);
        } else {
            int k = i - NQ * 8;
            int rr = k >> 3, s = k & 7;
            cpa16(sbase + OFF_SK * 2 + (rr * SK_S + s * 8) * 2, kp + rr * HD + s * 8);
        }
    }
    asm volatile("cp.async.commit_group;");
    asm volatile("cp.async.wait_group 0;");
    __syncthreads();

    // ---- column L2 norms -> rs[128] (warp w handles 8 channels) ----
    {
#pragma unroll
        for (int cc = 0; cc < 8; cc++) {
            int ch = wid * 8 + cc;
            float ss = 0.0f;
            if (ch < 64) {
                for (int i = lane; i < 112; i += 32) {
                    float v = __half2float(sQ[i * SQ_S + ch]); ss += v * v;
                }
            } else {
                int e = ch - 64;
                for (int i = lane; i < 256; i += 32) {
                    float v = __half2float(sK[i * SK_S + e]); ss += v * v;
                }
            }
#pragma unroll
            for (int o = 16; o; o >>= 1) ss += __shfl_xor_sync(0xffffffffu, ss, o);
            if (lane == 0) rs[ch] = 1.0f / fmaxf(sqrtf(ss), 1e-12f);
        }
    }
    __syncthreads();

    // ---- P1: qm[64,256] = q @ qmH^T -> hM (A via trans-ldsm from natural sQ) ----
    {
        const int mb = (wid & 3) * 16;
        const int nb = (wid >> 2) * 64;
        const uint32_t aBase = sbase +
            ((jj + (g >> 1) * 8) * SQ_S + mb + (g & 1) * 8) * 2;
        float acc[8][4];
#pragma unroll
        for (int i = 0; i < 8; i++)
#pragma unroll
            for (int k = 0; k < 4; k++) acc[i][k] = 0.0f;
        const int k0l = 2 * qq;
#pragma unroll
        for (int kk = 0; kk < 7; kk++) {
            uint32_t af[4];
            ldsm4t(af[0], af[1], af[2], af[3], aBase + kk * 16 * SQ_S * 2);
#pragma unroll
            for (int nb8 = 0; nb8 < 8; nb8++) {
                const __half* bp = qmH + (nb + nb8 * 8 + r) * 112 + kk * 16 + k0l;
                uint32_t bf[2];
                bf[0] = *(const uint32_t*)bp;
                bf[1] = *(const uint32_t*)(bp + 8);
                mma_f16(acc[nb8], af, bf);
            }
        }
#pragma unroll
        for (int nb8 = 0; nb8 < 8; nb8++) {
            int col = nb + nb8 * 8 + 2 * qq;
            *(__half2*)&hM[(mb + r) * HM_S + col]     = __floats2half2_rn(acc[nb8][0], acc[nb8][1]);
            *(__half2*)&hM[(mb + r + 8) * HM_S + col] = __floats2half2_rn(acc[nb8][2], acc[nb8][3]);
        }
    }
    __syncthreads();

    // ---- P2: S[64,64] = qm @ k^T -> sS fp32, scaled by temp*rs_q*rs_k ----
    {
        const int mb = (wid & 3) * 16;
        const int nb = (wid >> 2) * 16;
        const uint32_t aBase = sbase +
            (OFF_HM + (mb + jj + (g & 1) * 8) * HM_S + (g >> 1) * 8) * 2;
        const uint32_t bBase = sbase +
            (OFF_SK + (jj + (g >> 1) * 8) * SK_S + nb + (g & 1) * 8) * 2;
        float acc[2][4];
#pragma unroll
        for (int i = 0; i < 2; i++)
#pragma unroll
            for (int k = 0; k < 4; k++) acc[i][k] = 0.0f;
#pragma unroll
        for (int kk = 0; kk < 16; kk++) {
            uint32_t af[4], b0, b1, b2, b3;
            ldsm4(af[0], af[1], af[2], af[3], aBase + kk * 32);
            ldsm4t(b0, b1, b2, b3, bBase + kk * 16 * SK_S * 2);
            uint32_t bfA[2] = {b0, b2}, bfB[2] = {b1, b3};
            mma_f16(acc[0], af, bfA);
            mma_f16(acc[1], af, bfB);
        }
        const float tval = temp[h];
        const float rq0 = rs[mb + r] * tval;
        const float rq8 = rs[mb + r + 8] * tval;
#pragma unroll
        for (int t = 0; t < 2; t++) {
            int col = nb + t * 8 + 2 * qq;
            const float rk0 = rs[64 + col], rk1 = rs[64 + col + 1];
            sS[(mb + r) * SS_S + col]         = acc[t][0] * rq0 * rk0;
            sS[(mb + r) * SS_S + col + 1]     = acc[t][1] * rq0 * rk1;
            sS[(mb + r + 8) * SS_S + col]     = acc[t][2] * rq8 * rk0;
            sS[(mb + r + 8) * SS_S + col + 1] = acc[t][3] * rq8 * rk1;
        }
    }
    __syncthreads();

    // ---- parallel softmax: 8 threads per row, registers only ----
    {
        const int row = tid >> 3, sub = tid & 7;
        float v[8];
#pragma unroll
        for (int i = 0; i < 8; i++) v[i] = sS[row * SS_S + sub + 8 * i];
        float mx = v[0];
#pragma unroll
        for (int i = 1; i < 8; i++) mx = fmaxf(mx, v[i]);
#pragma unroll
        for (int o = 1; o < 8; o <<= 1) mx = fmaxf(mx, __shfl_xor_sync(0xffffffffu, mx, o));
        float sum = 0.0f;
#pragma unroll
        for (int i = 0; i < 8; i++) { v[i] = __expf(v[i] - mx); sum += v[i]; }
#pragma unroll
        for (int o = 1; o < 8; o <<= 1) sum += __shfl_xor_sync(0xffffffffu, sum, o);
        const float inv = 1.0f / sum;
        __syncthreads();                       // all reads done before fp16 overwrite
        __half* pp = (__half*)sS;              // hP view, row stride HP_S halves
#pragma unroll
        for (int i = 0; i < 8; i++)
            pp[row * HP_S + sub + 8 * i] = __float2half(v[i] * inv);
    }
    __syncthreads();

    // ---- P4: x[64,256] = P @ v^T -> hM (v B-frags from contiguous global) ----
    {
        const int mb = (wid & 3) * 16;
        const int nb = (wid >> 2) * 64;
        const uint32_t aBase = sbase +
            ((mb + jj + (g & 1) * 8) * HP_S + (g >> 1) * 8) * 2;
        float acc[8][4];
#pragma unroll
        for (int i = 0; i < 8; i++)
#pragma unroll
            for (int k = 0; k < 4; k++) acc[i][k] = 0.0f;
        const int k0l = 2 * qq;
#pragma unroll
        for (int kk = 0; kk < 4; kk++) {
            uint32_t af[4];
            ldsm4(af[0], af[1], af[2], af[3], aBase + kk * 32);
#pragma unroll
            for (int nb8 = 0; nb8 < 8; nb8++) {
                const int row = nb + nb8 * 8 + r;
                uint32_t bf[2] = {0u, 0u};
                if (row < NT) {
                    const __half* bp = vp + row * HD + kk * 16 + k0l;
                    bf[0] = *(const uint32_t*)bp;
                    bf[1] = *(const uint32_t*)(bp + 8);
                }
                mma_f16(acc[nb8], af, bf);
            }
        }
#pragma unroll
        for (int nb8 = 0; nb8 < 8; nb8++) {
            int col = nb + nb8 * 8 + 2 * qq;
            *(__half2*)&hM[(mb + r) * HM_S + col]     = __floats2half2_rn(acc[nb8][0], acc[nb8][1]);
            *(__half2*)&hM[(mb + r + 8) * HM_S + col] = __floats2half2_rn(acc[nb8][2], acc[nb8][3]);
        }
    }
    __syncthreads();

    // ---- P5: out[64,128] = x @ xmH^T -> sOut fp32 [q][d] (overlays sK) ----
    {
        const int mb = (wid & 3) * 16;
        const int nb = (wid >> 2) * 32;
        const uint32_t aBase = sbase +
            (OFF_HM + (mb + jj + (g & 1) * 8) * HM_S + (g >> 1) * 8) * 2;
        float acc[4][4];
#pragma unroll
        for (int i = 0; i < 4; i++)
#pragma unroll
            for (int k = 0; k < 4; k++) acc[i][k] = 0.0f;
        const int k0l = 2 * qq;
#pragma unroll
        for (int kk = 0; kk < 16; kk++) {
            uint32_t af[4];
            ldsm4(af[0], af[1], af[2], af[3], aBase + kk * 32);
#pragma unroll
            for (int nb8 = 0; nb8 < 4; nb8++) {
                const __half* bp = xmH + (nb + nb8 * 8 + r) * 256 + kk * 16 + k0l;
                uint32_t bf[2];
                bf[0] = *(const uint32_t*)bp;
                bf[1] = *(const uint32_t*)(bp + 8);
                mma_f16(acc[nb8], af, bf);
            }
        }
#pragma unroll
        for (int nb8 = 0; nb8 < 4; nb8++) {
            int q0 = nb + nb8 * 8 + 2 * qq;
            int d0 = mb + r;
            sOut[q0 * SO_S + d0]           = acc[nb8][0];
            sOut[(q0 + 1) * SO_S + d0]     = acc[nb8][1];
            sOut[q0 * SO_S + d0 + 8]       = acc[nb8][2];
            sOut[(q0 + 1) * SO_S + d0 + 8] = acc[nb8][3];
        }
    }
    __syncthreads();

    // ---- epilogue: coalesced fp16 store of q<100 rows (row-major y) ----
    for (int i = tid; i < NQ * 32; i += 512) {
        int q = i >> 5, c = i & 31;
        float a0 = sOut[q * SO_S + 2 * c];
        float a1 = sOut[q * SO_S + 2 * c + 1];
        *(__half2*)&y[((size_t)q * BSZ + b) * E + h * HD + 2 * c] =
            __floats2half2_rn(a0, a1);
    }
}

// ---------------------------------------------------------------------------
// Launch: f2h_all(1), norm_map(2), gemm_q(3), gemm_k(4=profiled), gemm_v(5),
//         attn(6), gemm_out(7)
// ---------------------------------------------------------------------------
extern "C" void kernel_launch(void* const* d_in, const int* in_sizes, int n_in,
                              void* d_out, int out_size)
{
    const float* query = (const float*)d_in[0];
    const float* key   = (const float*)d_in[1];
    const float* value = (const float*)d_in[2];
    const float* ipw   = (const float*)d_in[3];
    const float* ipb   = (const float*)d_in[4];
    const float* opw   = (const float*)d_in[5];
    const float* opb   = (const float*)d_in[6];
    const float* temp  = (const float*)d_in[7];
    const float* qmap  = (const float*)d_in[8];
    const float* xmap  = (const float*)d_in[9];
    float* out = (float*)d_out;

    __half *qh, *kh, *vh, *wh, *owh, *yh, *qmH, *xmH, *qph, *kph, *vph;
    cudaGetSymbolAddress((void**)&qh,  g_qh);
    cudaGetSymbolAddress((void**)&kh,  g_kh);
    cudaGetSymbolAddress((void**)&vh,  g_vh);
    cudaGetSymbolAddress((void**)&wh,  g_wh);
    cudaGetSymbolAddress((void**)&owh, g_owh);
    cudaGetSymbolAddress((void**)&yh,  g_yh);
    cudaGetSymbolAddress((void**)&qmH, g_qmH);
    cudaGetSymbolAddress((void**)&xmH, g_xmH);
    cudaGetSymbolAddress((void**)&qph, g_qph);
    cudaGetSymbolAddress((void**)&kph, g_kph);
    cudaGetSymbolAddress((void**)&vph, g_vph);

    cudaFuncSetAttribute(gemm_h<true>,  cudaFuncAttributeMaxDynamicSharedMemorySize, GEMM_SMEM);
    cudaFuncSetAttribute(gemm_h<false>, cudaFuncAttributeMaxDynamicSharedMemorySize, GEMM_SMEM);
    cudaFuncSetAttribute(attn_tc, cudaFuncAttributeMaxDynamicSharedMemorySize,
                         ATTN_SMEM_BYTES);

    dim3 gq(6, (NQ * BSZ) / 128);
    dim3 gk(6, (NT * BSZ) / 128);

    f2h_all<<<(TOT4 + 255) / 256, 256>>>(
        (const float4*)query, (const float4*)key, (const float4*)value,
        (const float4*)ipw, (const float4*)opw,
        (__half2*)qh, (__half2*)kh, (__half2*)vh, (__half2*)wh, (__half2*)owh);
    norm_map_h<<<48, 256>>>(qmap, xmap, qmH, xmH);
    gemm_h<true><<<gq, 256, GEMM_SMEM>>>(qh, wh,             ipb,         qph, NQ);
    gemm_h<true><<<gk, 256, GEMM_SMEM>>>(kh, wh + E * E,     ipb + E,     kph, NT);
    gemm_h<true><<<gk, 256, GEMM_SMEM>>>(vh, wh + 2 * E * E, ipb + 2 * E, vph, NT);
    attn_tc<<<BH, 512, ATTN_SMEM_BYTES>>>(qph, kph, vph, qmH, xmH, temp, yh);
    gemm_h<false><<<gq, 256, GEMM_SMEM>>>(yh, owh, opb, out, 0);
}